// round 4
// baseline (speedup 1.0000x reference)
#include <cuda_runtime.h>
#include <cstdint>

#define MAXN 50176
#define MAXE 800000

// ---------------- scratch (device globals; no allocation allowed) -----------
__device__ int   g_is64;                           // edge dtype flag
__device__ int   g_src[MAXE];                      // decoded src ids (int32)
__device__ int   g_dst[MAXE];                      // decoded dst ids (int32)
__device__ int   g_cnt[MAXN + 1];                  // histogram
__device__ int   g_rowptr[MAXN + 1];               // CSR row pointers
__device__ int   g_cur[MAXN + 1];                  // fill cursors
__device__ int   g_csr[MAXE];                      // src ids grouped by dst
__device__ float g_aggm[(size_t)MAXN * 128];       // layer-1 mean aggregation
__device__ float g_h[(size_t)MAXN * 128];          // layer-1 output
__device__ float g_t2[(size_t)MAXN * 64];          // h @ W2l
__device__ float g_aggm2[(size_t)MAXN * 64];       // layer-2 mean aggregation

// ---------------- edge dtype detect + decode ---------------------------------
// If edge_index is int64 (little-endian, values in [0, 50000)), every odd
// 32-bit word of the buffer is a zero high-word. If int32, odd words are
// random node ids; P(2048-sample all zero) ~ 0.
__global__ void detect_kernel(const int* __restrict__ w) {
    __shared__ int nonzero;
    if (threadIdx.x == 0) nonzero = 0;
    __syncthreads();
    int nz = 0;
    for (int i = threadIdx.x; i < 1024; i += 256)
        if (w[2 * i + 1] != 0) nz = 1;
    if (nz) nonzero = 1;              // benign race
    __syncthreads();
    if (threadIdx.x == 0) g_is64 = (nonzero == 0) ? 1 : 0;
}

__global__ void convert_kernel(const int* __restrict__ w, int E, int N) {
    int e = blockIdx.x * blockDim.x + threadIdx.x;
    if (e >= E) return;
    int s, d;
    if (g_is64) {                     // int64 layout: low word at 2*idx
        s = w[2 * e];
        d = w[2 * (E + e)];
    } else {                          // int32 layout
        s = w[e];
        d = w[E + e];
    }
    // clamp as insurance: wrong values -> wrong answer, never a trap
    s = min(max(s, 0), N - 1);
    d = min(max(d, 0), N - 1);
    g_src[e] = s;
    g_dst[e] = d;
}

// ---------------- CSR build --------------------------------------------------
__global__ void zero_cnt_kernel(int N) {
    int i = blockIdx.x * blockDim.x + threadIdx.x;
    if (i <= N) g_cnt[i] = 0;
}

__global__ void hist_kernel(int E) {
    int e = blockIdx.x * blockDim.x + threadIdx.x;
    if (e < E) atomicAdd(&g_cnt[g_dst[e]], 1);
}

// single-block exclusive scan over N counts -> rowptr, cur; rowptr[N] = E
__global__ void __launch_bounds__(1024) scan_kernel(int N) {
    __shared__ int part[1024];
    int t = threadIdx.x;
    int CH = (N + 1023) >> 10;
    int beg = t * CH;
    int end = min(beg + CH, N);
    int s = 0;
    for (int i = beg; i < end; i++) s += g_cnt[i];
    part[t] = s;
    __syncthreads();
    for (int off = 1; off < 1024; off <<= 1) {
        int v = (t >= off) ? part[t - off] : 0;
        __syncthreads();
        part[t] += v;
        __syncthreads();
    }
    int run = (t == 0) ? 0 : part[t - 1];
    for (int i = beg; i < end; i++) {
        int c = g_cnt[i];
        g_rowptr[i] = run;
        g_cur[i] = run;
        run += c;
    }
    if (t == 0) g_rowptr[N] = part[1023];
}

__global__ void fill_kernel(int E) {
    int e = blockIdx.x * blockDim.x + threadIdx.x;
    if (e >= E) return;
    int pos = atomicAdd(&g_cur[g_dst[e]], 1);
    g_csr[pos] = g_src[e];
}

// ---------------- gather-mean aggregation ------------------------------------
// 128-ch from input x: one warp per node, lane holds float4
__global__ void agg_mean128_kernel(const float* __restrict__ x, int N) {
    int warp = (int)(((size_t)blockIdx.x * blockDim.x + threadIdx.x) >> 5);
    int lane = threadIdx.x & 31;
    if (warp >= N) return;
    int beg = g_rowptr[warp];
    int end = g_rowptr[warp + 1];
    float4 acc0 = make_float4(0.f, 0.f, 0.f, 0.f);
    float4 acc1 = make_float4(0.f, 0.f, 0.f, 0.f);
    int i = beg;
    for (; i + 1 < end; i += 2) {
        int s0 = g_csr[i];
        int s1 = g_csr[i + 1];
        float4 v0 = reinterpret_cast<const float4*>(x + (size_t)s0 * 128)[lane];
        float4 v1 = reinterpret_cast<const float4*>(x + (size_t)s1 * 128)[lane];
        acc0.x += v0.x; acc0.y += v0.y; acc0.z += v0.z; acc0.w += v0.w;
        acc1.x += v1.x; acc1.y += v1.y; acc1.z += v1.z; acc1.w += v1.w;
    }
    if (i < end) {
        int s0 = g_csr[i];
        float4 v0 = reinterpret_cast<const float4*>(x + (size_t)s0 * 128)[lane];
        acc0.x += v0.x; acc0.y += v0.y; acc0.z += v0.z; acc0.w += v0.w;
    }
    int deg = end - beg;
    float rd = (deg > 0) ? (1.0f / (float)deg) : 0.0f;
    float4 r;
    r.x = (acc0.x + acc1.x) * rd;
    r.y = (acc0.y + acc1.y) * rd;
    r.z = (acc0.z + acc1.z) * rd;
    r.w = (acc0.w + acc1.w) * rd;
    reinterpret_cast<float4*>(g_aggm + (size_t)warp * 128)[lane] = r;
}

// 64-ch from g_t2: one warp per node, lane holds float2
__global__ void agg_mean64_kernel(int N) {
    int warp = (int)(((size_t)blockIdx.x * blockDim.x + threadIdx.x) >> 5);
    int lane = threadIdx.x & 31;
    if (warp >= N) return;
    int beg = g_rowptr[warp];
    int end = g_rowptr[warp + 1];
    float2 acc0 = make_float2(0.f, 0.f);
    float2 acc1 = make_float2(0.f, 0.f);
    int i = beg;
    for (; i + 1 < end; i += 2) {
        int s0 = g_csr[i];
        int s1 = g_csr[i + 1];
        float2 v0 = reinterpret_cast<const float2*>(g_t2 + (size_t)s0 * 64)[lane];
        float2 v1 = reinterpret_cast<const float2*>(g_t2 + (size_t)s1 * 64)[lane];
        acc0.x += v0.x; acc0.y += v0.y;
        acc1.x += v1.x; acc1.y += v1.y;
    }
    if (i < end) {
        int s0 = g_csr[i];
        float2 v0 = reinterpret_cast<const float2*>(g_t2 + (size_t)s0 * 64)[lane];
        acc0.x += v0.x; acc0.y += v0.y;
    }
    int deg = end - beg;
    float rd = (deg > 0) ? (1.0f / (float)deg) : 0.0f;
    float2 r;
    r.x = (acc0.x + acc1.x) * rd;
    r.y = (acc0.y + acc1.y) * rd;
    reinterpret_cast<float2*>(g_aggm2 + (size_t)warp * 64)[lane] = r;
}

// ---------------- fused GEMM (K = 128, K-chunked, static smem) ----------------
// MODE 1: g_h  = relu(g_aggm @ Wa + bias + Bx @ Wb)          (OUT=128, dual)
// MODE 2: g_t2 = g_h @ Wa                                     (OUT=64)
// MODE 3: outp = g_h @ Wa + bias + g_aggm2                    (OUT=64, side)
template<int MODE>
__global__ void __launch_bounds__(256)
sage_gemm(const float* __restrict__ Bx, const float* __restrict__ Wa,
          const float* __restrict__ Wb, const float* __restrict__ bias,
          float* __restrict__ outp, int nNodes) {
    constexpr int  OUT     = (MODE == 1) ? 128 : 64;
    constexpr bool DUAL    = (MODE == 1);
    constexpr bool RELU    = (MODE == 1);
    constexpr bool HASBIAS = (MODE != 2);
    constexpr bool SIDE    = (MODE == 3);
    constexpr int CT = OUT / 4;           // threads along output columns
    constexpr int GROUPS = 256 / CT;      // node groups
    constexpr int TILE = GROUPS * 4;      // nodes per block tile
    constexpr int KC = 32;                // K-chunk
    constexpr int ASTR = KC + 4;          // padded smem row stride

    __shared__ float Ws[KC * OUT];
    __shared__ float Wbs[DUAL ? KC * OUT : 4];
    __shared__ float As[TILE * ASTR];
    __shared__ float Bs[DUAL ? TILE * ASTR : 4];

    const float* A = (MODE == 1) ? g_aggm : g_h;
    float* op = (MODE == 1) ? g_h : ((MODE == 2) ? g_t2 : outp);

    const int cidx = threadIdx.x % CT;
    const int grp  = threadIdx.x / CT;
    const int c0   = cidx * 4;
    const int ln0  = grp * 4;

    int base = blockIdx.x * TILE;

    float acc[4][4];
#pragma unroll
    for (int n = 0; n < 4; n++)
#pragma unroll
        for (int c = 0; c < 4; c++) acc[n][c] = 0.f;

    for (int ck = 0; ck < 4; ck++) {
        __syncthreads();
        for (int i = threadIdx.x; i < KC * OUT / 4; i += 256) {
            int row = i / (OUT / 4);
            int c4  = i % (OUT / 4);
            reinterpret_cast<float4*>(Ws)[row * (OUT / 4) + c4] =
                reinterpret_cast<const float4*>(Wa)[(ck * KC + row) * (OUT / 4) + c4];
        }
        if constexpr (DUAL) {
            for (int i = threadIdx.x; i < KC * OUT / 4; i += 256) {
                int row = i / (OUT / 4);
                int c4  = i % (OUT / 4);
                reinterpret_cast<float4*>(Wbs)[row * (OUT / 4) + c4] =
                    reinterpret_cast<const float4*>(Wb)[(ck * KC + row) * (OUT / 4) + c4];
            }
        }
        for (int i = threadIdx.x; i < TILE * (KC / 4); i += 256) {
            int r  = i / (KC / 4);
            int c4 = i % (KC / 4);
            int node = base + r;
            float4 v = make_float4(0.f, 0.f, 0.f, 0.f);
            if (node < nNodes)
                v = reinterpret_cast<const float4*>(A + (size_t)node * 128)[ck * (KC / 4) + c4];
            *reinterpret_cast<float4*>(As + r * ASTR + c4 * 4) = v;
        }
        if constexpr (DUAL) {
            for (int i = threadIdx.x; i < TILE * (KC / 4); i += 256) {
                int r  = i / (KC / 4);
                int c4 = i % (KC / 4);
                int node = base + r;
                float4 v = make_float4(0.f, 0.f, 0.f, 0.f);
                if (node < nNodes)
                    v = reinterpret_cast<const float4*>(Bx + (size_t)node * 128)[ck * (KC / 4) + c4];
                *reinterpret_cast<float4*>(Bs + r * ASTR + c4 * 4) = v;
            }
        }
        __syncthreads();

#pragma unroll 4
        for (int k = 0; k < KC; k++) {
            float4 w = *reinterpret_cast<const float4*>(Ws + k * OUT + c0);
#pragma unroll
            for (int n = 0; n < 4; n++) {
                float a = As[(ln0 + n) * ASTR + k];
                acc[n][0] = fmaf(a, w.x, acc[n][0]);
                acc[n][1] = fmaf(a, w.y, acc[n][1]);
                acc[n][2] = fmaf(a, w.z, acc[n][2]);
                acc[n][3] = fmaf(a, w.w, acc[n][3]);
            }
            if constexpr (DUAL) {
                float4 w2 = *reinterpret_cast<const float4*>(Wbs + k * OUT + c0);
#pragma unroll
                for (int n = 0; n < 4; n++) {
                    float b = Bs[(ln0 + n) * ASTR + k];
                    acc[n][0] = fmaf(b, w2.x, acc[n][0]);
                    acc[n][1] = fmaf(b, w2.y, acc[n][1]);
                    acc[n][2] = fmaf(b, w2.z, acc[n][2]);
                    acc[n][3] = fmaf(b, w2.w, acc[n][3]);
                }
            }
        }
    }

    float4 bv = make_float4(0.f, 0.f, 0.f, 0.f);
    if constexpr (HASBIAS) bv = reinterpret_cast<const float4*>(bias)[cidx];

#pragma unroll
    for (int n = 0; n < 4; n++) {
        int node = base + ln0 + n;
        if (node >= nNodes) continue;
        float r0 = acc[n][0], r1 = acc[n][1], r2 = acc[n][2], r3 = acc[n][3];
        if constexpr (HASBIAS) { r0 += bv.x; r1 += bv.y; r2 += bv.z; r3 += bv.w; }
        if constexpr (SIDE) {
            float4 sv = *reinterpret_cast<const float4*>(g_aggm2 + (size_t)node * 64 + c0);
            r0 += sv.x; r1 += sv.y; r2 += sv.z; r3 += sv.w;
        }
        if constexpr (RELU) {
            r0 = fmaxf(r0, 0.f); r1 = fmaxf(r1, 0.f);
            r2 = fmaxf(r2, 0.f); r3 = fmaxf(r3, 0.f);
        }
        *reinterpret_cast<float4*>(op + (size_t)node * OUT + c0) =
            make_float4(r0, r1, r2, r3);
    }
}

// ---------------- launch -------------------------------------------------------
extern "C" void kernel_launch(void* const* d_in, const int* in_sizes, int n_in,
                              void* d_out, int out_size) {
    const float* x       = (const float*)d_in[0];
    const int*   ei_w    = (const int*)d_in[1];     // raw 32-bit words of edge_index
    const float* W1l     = (const float*)d_in[2];
    const float* b1      = (const float*)d_in[3];
    const float* W1r     = (const float*)d_in[4];
    const float* W2l     = (const float*)d_in[5];
    const float* b2      = (const float*)d_in[6];
    const float* W2r     = (const float*)d_in[7];
    float* out = (float*)d_out;

    int N = in_sizes[0] / 128;
    int E = in_sizes[1] / 2;   // element count -> edges (same for i32/i64)

    // --- decode edge index (dtype-robust) ---
    detect_kernel<<<1, 256>>>(ei_w);
    convert_kernel<<<(E + 255) / 256, 256>>>(ei_w, E, N);

    // --- CSR build (int atomics only) ---
    zero_cnt_kernel<<<(N + 256) / 256, 256>>>(N);
    hist_kernel<<<(E + 255) / 256, 256>>>(E);
    scan_kernel<<<1, 1024>>>(N);
    fill_kernel<<<(E + 255) / 256, 256>>>(E);

    // --- layer 1: mean-gather then dual GEMM ---
    {
        size_t threads = (size_t)N * 32;
        agg_mean128_kernel<<<(int)((threads + 255) / 256), 256>>>(x, N);
    }
    sage_gemm<1><<<(N + 31) / 32, 256>>>(x, W1l, W1r, b1, nullptr, N);

    // --- layer 2: transform, mean-gather, final GEMM ---
    sage_gemm<2><<<(N + 63) / 64, 256>>>(nullptr, W2l, nullptr, nullptr, nullptr, N);
    {
        size_t threads = (size_t)N * 32;
        agg_mean64_kernel<<<(int)((threads + 255) / 256), 256>>>(N);
    }
    sage_gemm<3><<<(N + 63) / 64, 256>>>(nullptr, W2r, nullptr, b2, out, N);
}

// round 5
// speedup vs baseline: 1.0232x; 1.0232x over previous
#include <cuda_runtime.h>
#include <cstdint>

#define MAXN 50176
#define MAXE 800000

// ---------------- scratch (device globals; no allocation allowed) -----------
__device__ int   g_is64;                           // edge dtype flag
__device__ int   g_src[MAXE];                      // decoded src ids (int32)
__device__ int   g_dst[MAXE];                      // decoded dst ids (int32)
__device__ int   g_cnt[MAXN + 1];                  // histogram
__device__ int   g_rowptr[MAXN + 1];               // CSR row pointers
__device__ int   g_cur[MAXN + 1];                  // fill cursors
__device__ int   g_csr[MAXE];                      // src ids grouped by dst
__device__ float g_aggm[(size_t)MAXN * 128];       // layer-1 mean aggregation
__device__ float g_h[(size_t)MAXN * 128];          // layer-1 output
__device__ float g_t2[(size_t)MAXN * 64];          // h @ W2l
__device__ float g_aggm2[(size_t)MAXN * 64];       // layer-2 mean aggregation

// ---------------- packed f32x2 helpers ---------------------------------------
__device__ __forceinline__ void fma2(unsigned long long& acc,
                                     unsigned long long a,
                                     unsigned long long b) {
    asm("fma.rn.f32x2 %0, %1, %2, %0;" : "+l"(acc) : "l"(a), "l"(b));
}
__device__ __forceinline__ unsigned long long pack2(float m) {
    unsigned long long r;
    unsigned int mi = __float_as_uint(m);
    asm("mov.b64 %0, {%1, %1};" : "=l"(r) : "r"(mi));
    return r;
}
__device__ __forceinline__ void unpack2(unsigned long long p, float& lo, float& hi) {
    unsigned int a, b;
    asm("mov.b64 {%0, %1}, %2;" : "=r"(a), "=r"(b) : "l"(p));
    lo = __uint_as_float(a);
    hi = __uint_as_float(b);
}

// ---------------- edge dtype detect ------------------------------------------
// int64 edge values < 50000 => every odd 32-bit word is zero. int32 => random.
__global__ void detect_kernel(const int* __restrict__ w) {
    __shared__ int nonzero;
    if (threadIdx.x == 0) nonzero = 0;
    __syncthreads();
    int nz = 0;
    for (int i = threadIdx.x; i < 1024; i += 256)
        if (w[2 * i + 1] != 0) nz = 1;
    if (nz) nonzero = 1;              // benign race
    __syncthreads();
    if (threadIdx.x == 0) g_is64 = (nonzero == 0) ? 1 : 0;
}

__global__ void zero_cnt_kernel(int N) {
    int i = blockIdx.x * blockDim.x + threadIdx.x;
    if (i <= N) g_cnt[i] = 0;
}

// decode edges AND histogram dst in one pass
__global__ void convert_hist_kernel(const int* __restrict__ w, int E, int N) {
    int e = blockIdx.x * blockDim.x + threadIdx.x;
    if (e >= E) return;
    int s, d;
    if (g_is64) {
        s = w[2 * e];
        d = w[2 * (E + e)];
    } else {
        s = w[e];
        d = w[E + e];
    }
    s = min(max(s, 0), N - 1);        // clamp: never trap on bad data
    d = min(max(d, 0), N - 1);
    g_src[e] = s;
    g_dst[e] = d;
    atomicAdd(&g_cnt[d], 1);
}

// single-block exclusive scan over N counts -> rowptr, cur; rowptr[N] = E
__global__ void __launch_bounds__(1024) scan_kernel(int N) {
    __shared__ int part[1024];
    int t = threadIdx.x;
    int CH = (N + 1023) >> 10;
    int beg = t * CH;
    int end = min(beg + CH, N);
    int s = 0;
    for (int i = beg; i < end; i++) s += g_cnt[i];
    part[t] = s;
    __syncthreads();
    for (int off = 1; off < 1024; off <<= 1) {
        int v = (t >= off) ? part[t - off] : 0;
        __syncthreads();
        part[t] += v;
        __syncthreads();
    }
    int run = (t == 0) ? 0 : part[t - 1];
    for (int i = beg; i < end; i++) {
        int c = g_cnt[i];
        g_rowptr[i] = run;
        g_cur[i] = run;
        run += c;
    }
    if (t == 0) g_rowptr[N] = part[1023];
}

__global__ void fill_kernel(int E) {
    int e = blockIdx.x * blockDim.x + threadIdx.x;
    if (e >= E) return;
    int pos = atomicAdd(&g_cur[g_dst[e]], 1);
    g_csr[pos] = g_src[e];
}

// ---------------- gather-mean aggregation ------------------------------------
__global__ void agg_mean128_kernel(const float* __restrict__ x, int N) {
    int warp = (int)(((size_t)blockIdx.x * blockDim.x + threadIdx.x) >> 5);
    int lane = threadIdx.x & 31;
    if (warp >= N) return;
    int beg = g_rowptr[warp];
    int end = g_rowptr[warp + 1];
    float4 acc0 = make_float4(0.f, 0.f, 0.f, 0.f);
    float4 acc1 = make_float4(0.f, 0.f, 0.f, 0.f);
    int i = beg;
    for (; i + 1 < end; i += 2) {
        int s0 = g_csr[i];
        int s1 = g_csr[i + 1];
        float4 v0 = reinterpret_cast<const float4*>(x + (size_t)s0 * 128)[lane];
        float4 v1 = reinterpret_cast<const float4*>(x + (size_t)s1 * 128)[lane];
        acc0.x += v0.x; acc0.y += v0.y; acc0.z += v0.z; acc0.w += v0.w;
        acc1.x += v1.x; acc1.y += v1.y; acc1.z += v1.z; acc1.w += v1.w;
    }
    if (i < end) {
        int s0 = g_csr[i];
        float4 v0 = reinterpret_cast<const float4*>(x + (size_t)s0 * 128)[lane];
        acc0.x += v0.x; acc0.y += v0.y; acc0.z += v0.z; acc0.w += v0.w;
    }
    int deg = end - beg;
    float rd = (deg > 0) ? (1.0f / (float)deg) : 0.0f;
    float4 r;
    r.x = (acc0.x + acc1.x) * rd;
    r.y = (acc0.y + acc1.y) * rd;
    r.z = (acc0.z + acc1.z) * rd;
    r.w = (acc0.w + acc1.w) * rd;
    reinterpret_cast<float4*>(g_aggm + (size_t)warp * 128)[lane] = r;
}

__global__ void agg_mean64_kernel(int N) {
    int warp = (int)(((size_t)blockIdx.x * blockDim.x + threadIdx.x) >> 5);
    int lane = threadIdx.x & 31;
    if (warp >= N) return;
    int beg = g_rowptr[warp];
    int end = g_rowptr[warp + 1];
    float2 acc0 = make_float2(0.f, 0.f);
    float2 acc1 = make_float2(0.f, 0.f);
    int i = beg;
    for (; i + 1 < end; i += 2) {
        int s0 = g_csr[i];
        int s1 = g_csr[i + 1];
        float2 v0 = reinterpret_cast<const float2*>(g_t2 + (size_t)s0 * 64)[lane];
        float2 v1 = reinterpret_cast<const float2*>(g_t2 + (size_t)s1 * 64)[lane];
        acc0.x += v0.x; acc0.y += v0.y;
        acc1.x += v1.x; acc1.y += v1.y;
    }
    if (i < end) {
        int s0 = g_csr[i];
        float2 v0 = reinterpret_cast<const float2*>(g_t2 + (size_t)s0 * 64)[lane];
        acc0.x += v0.x; acc0.y += v0.y;
    }
    int deg = end - beg;
    float rd = (deg > 0) ? (1.0f / (float)deg) : 0.0f;
    float2 r;
    r.x = (acc0.x + acc1.x) * rd;
    r.y = (acc0.y + acc1.y) * rd;
    reinterpret_cast<float2*>(g_aggm2 + (size_t)warp * 64)[lane] = r;
}

// ---------------- fused GEMM (K = 128, K-chunked, packed f32x2) ----------------
// MODE 1: g_h  = relu(g_aggm @ Wa + bias + Bx @ Wb)          (OUT=128, dual)
// MODE 2: g_t2 = g_h @ Wa                                     (OUT=64)
// MODE 3: outp = g_h @ Wa + bias + g_aggm2                    (OUT=64, side)
template<int MODE>
__global__ void __launch_bounds__(256)
sage_gemm(const float* __restrict__ Bx, const float* __restrict__ Wa,
          const float* __restrict__ Wb, const float* __restrict__ bias,
          float* __restrict__ outp, int nNodes) {
    constexpr int  OUT     = (MODE == 1) ? 128 : 64;
    constexpr bool DUAL    = (MODE == 1);
    constexpr bool RELU    = (MODE == 1);
    constexpr bool HASBIAS = (MODE != 2);
    constexpr bool SIDE    = (MODE == 3);
    constexpr int CT = OUT / 4;           // threads along output columns
    constexpr int GROUPS = 256 / CT;      // node groups
    constexpr int TILE = GROUPS * 4;      // nodes per block tile
    constexpr int KC = 32;                // K-chunk
    constexpr int ASTR = KC + 4;          // padded smem row stride

    __shared__ __align__(16) float Ws[KC * OUT];
    __shared__ __align__(16) float Wbs[DUAL ? KC * OUT : 4];
    __shared__ __align__(16) float As[TILE * ASTR];
    __shared__ __align__(16) float Bs[DUAL ? TILE * ASTR : 4];

    const float* A = (MODE == 1) ? g_aggm : g_h;
    float* op = (MODE == 1) ? g_h : ((MODE == 2) ? g_t2 : outp);

    const int cidx = threadIdx.x % CT;
    const int grp  = threadIdx.x / CT;
    const int c0   = cidx * 4;
    const int ln0  = grp * 4;

    int base = blockIdx.x * TILE;

    unsigned long long acc01[4] = {0ull, 0ull, 0ull, 0ull};
    unsigned long long acc23[4] = {0ull, 0ull, 0ull, 0ull};

    for (int ck = 0; ck < 4; ck++) {
        __syncthreads();
        for (int i = threadIdx.x; i < KC * OUT / 4; i += 256) {
            int row = i / (OUT / 4);
            int c4  = i % (OUT / 4);
            reinterpret_cast<float4*>(Ws)[row * (OUT / 4) + c4] =
                reinterpret_cast<const float4*>(Wa)[(ck * KC + row) * (OUT / 4) + c4];
        }
        if constexpr (DUAL) {
            for (int i = threadIdx.x; i < KC * OUT / 4; i += 256) {
                int row = i / (OUT / 4);
                int c4  = i % (OUT / 4);
                reinterpret_cast<float4*>(Wbs)[row * (OUT / 4) + c4] =
                    reinterpret_cast<const float4*>(Wb)[(ck * KC + row) * (OUT / 4) + c4];
            }
        }
        for (int i = threadIdx.x; i < TILE * (KC / 4); i += 256) {
            int r  = i / (KC / 4);
            int c4 = i % (KC / 4);
            int node = base + r;
            float4 v = make_float4(0.f, 0.f, 0.f, 0.f);
            if (node < nNodes)
                v = reinterpret_cast<const float4*>(A + (size_t)node * 128)[ck * (KC / 4) + c4];
            *reinterpret_cast<float4*>(As + r * ASTR + c4 * 4) = v;
        }
        if constexpr (DUAL) {
            for (int i = threadIdx.x; i < TILE * (KC / 4); i += 256) {
                int r  = i / (KC / 4);
                int c4 = i % (KC / 4);
                int node = base + r;
                float4 v = make_float4(0.f, 0.f, 0.f, 0.f);
                if (node < nNodes)
                    v = reinterpret_cast<const float4*>(Bx + (size_t)node * 128)[ck * (KC / 4) + c4];
                *reinterpret_cast<float4*>(Bs + r * ASTR + c4 * 4) = v;
            }
        }
        __syncthreads();

#pragma unroll 4
        for (int k = 0; k < KC; k++) {
            ulonglong2 w = *reinterpret_cast<const ulonglong2*>(Ws + k * OUT + c0);
            {
                unsigned long long m;
                m = pack2(As[(ln0 + 0) * ASTR + k]); fma2(acc01[0], w.x, m); fma2(acc23[0], w.y, m);
                m = pack2(As[(ln0 + 1) * ASTR + k]); fma2(acc01[1], w.x, m); fma2(acc23[1], w.y, m);
                m = pack2(As[(ln0 + 2) * ASTR + k]); fma2(acc01[2], w.x, m); fma2(acc23[2], w.y, m);
                m = pack2(As[(ln0 + 3) * ASTR + k]); fma2(acc01[3], w.x, m); fma2(acc23[3], w.y, m);
            }
            if constexpr (DUAL) {
                ulonglong2 w2 = *reinterpret_cast<const ulonglong2*>(Wbs + k * OUT + c0);
                unsigned long long m;
                m = pack2(Bs[(ln0 + 0) * ASTR + k]); fma2(acc01[0], w2.x, m); fma2(acc23[0], w2.y, m);
                m = pack2(Bs[(ln0 + 1) * ASTR + k]); fma2(acc01[1], w2.x, m); fma2(acc23[1], w2.y, m);
                m = pack2(Bs[(ln0 + 2) * ASTR + k]); fma2(acc01[2], w2.x, m); fma2(acc23[2], w2.y, m);
                m = pack2(Bs[(ln0 + 3) * ASTR + k]); fma2(acc01[3], w2.x, m); fma2(acc23[3], w2.y, m);
            }
        }
    }

    float4 bv = make_float4(0.f, 0.f, 0.f, 0.f);
    if constexpr (HASBIAS) bv = reinterpret_cast<const float4*>(bias)[cidx];

#pragma unroll
    for (int n = 0; n < 4; n++) {
        int node = base + ln0 + n;
        if (node >= nNodes) continue;
        float r0, r1, r2, r3;
        unpack2(acc01[n], r0, r1);
        unpack2(acc23[n], r2, r3);
        if constexpr (HASBIAS) { r0 += bv.x; r1 += bv.y; r2 += bv.z; r3 += bv.w; }
        if constexpr (SIDE) {
            float4 sv = *reinterpret_cast<const float4*>(g_aggm2 + (size_t)node * 64 + c0);
            r0 += sv.x; r1 += sv.y; r2 += sv.z; r3 += sv.w;
        }
        if constexpr (RELU) {
            r0 = fmaxf(r0, 0.f); r1 = fmaxf(r1, 0.f);
            r2 = fmaxf(r2, 0.f); r3 = fmaxf(r3, 0.f);
        }
        *reinterpret_cast<float4*>(op + (size_t)node * OUT + c0) =
            make_float4(r0, r1, r2, r3);
    }
}

// ---------------- launch -------------------------------------------------------
extern "C" void kernel_launch(void* const* d_in, const int* in_sizes, int n_in,
                              void* d_out, int out_size) {
    const float* x       = (const float*)d_in[0];
    const int*   ei_w    = (const int*)d_in[1];     // raw 32-bit words of edge_index
    const float* W1l     = (const float*)d_in[2];
    const float* b1      = (const float*)d_in[3];
    const float* W1r     = (const float*)d_in[4];
    const float* W2l     = (const float*)d_in[5];
    const float* b2      = (const float*)d_in[6];
    const float* W2r     = (const float*)d_in[7];
    float* out = (float*)d_out;

    int N = in_sizes[0] / 128;
    int E = in_sizes[1] / 2;

    // --- decode + CSR build (int atomics only) ---
    detect_kernel<<<1, 256>>>(ei_w);
    zero_cnt_kernel<<<(N + 256) / 256, 256>>>(N);
    convert_hist_kernel<<<(E + 255) / 256, 256>>>(ei_w, E, N);
    scan_kernel<<<1, 1024>>>(N);
    fill_kernel<<<(E + 255) / 256, 256>>>(E);

    // --- layer 1: mean-gather then dual GEMM ---
    {
        size_t threads = (size_t)N * 32;
        agg_mean128_kernel<<<(int)((threads + 255) / 256), 256>>>(x, N);
    }
    sage_gemm<1><<<(N + 31) / 32, 256>>>(x, W1l, W1r, b1, nullptr, N);

    // --- layer 2: transform, mean-gather, final GEMM ---
    sage_gemm<2><<<(N + 63) / 64, 256>>>(nullptr, W2l, nullptr, nullptr, nullptr, N);
    {
        size_t threads = (size_t)N * 32;
        agg_mean64_kernel<<<(int)((threads + 255) / 256), 256>>>(N);
    }
    sage_gemm<3><<<(N + 63) / 64, 256>>>(nullptr, W2r, nullptr, b2, out, N);
}

// round 6
// speedup vs baseline: 1.3262x; 1.2961x over previous
#include <cuda_runtime.h>
#include <cstdint>

#define MAXN 50176
#define MAXE 800000
#define SCAN_BLK 256
#define NBLK ((MAXN + SCAN_BLK - 1) / SCAN_BLK)   // 196

// ---------------- scratch (device globals; no allocation allowed) -----------
__device__ int   g_is64;                           // edge dtype flag
__device__ int   g_src[MAXE];                      // decoded src ids (int32)
__device__ int   g_dst[MAXE];                      // decoded dst ids (int32)
__device__ int   g_cnt[MAXN + 1];                  // histogram
__device__ int   g_rowptr[MAXN + 1];               // CSR row pointers
__device__ int   g_cur[MAXN + 1];                  // fill cursors
__device__ int   g_csr[MAXE];                      // src ids grouped by dst
__device__ int   g_blksum[NBLK];                   // scan phase-1 block sums
__device__ int   g_blkoff[NBLK];                   // scan phase-2 block offsets
__device__ float g_aggm[(size_t)MAXN * 128];       // layer-1 mean aggregation
__device__ float g_h[(size_t)MAXN * 128];          // layer-1 output
__device__ float g_t2[(size_t)MAXN * 64];          // h @ W2l
__device__ float g_aggm2[(size_t)MAXN * 64];       // layer-2 mean aggregation

// ---------------- packed f32x2 helpers ---------------------------------------
__device__ __forceinline__ void fma2(unsigned long long& acc,
                                     unsigned long long a,
                                     unsigned long long b) {
    asm("fma.rn.f32x2 %0, %1, %2, %0;" : "+l"(acc) : "l"(a), "l"(b));
}
__device__ __forceinline__ unsigned long long pack2(float m) {
    unsigned long long r;
    unsigned int mi = __float_as_uint(m);
    asm("mov.b64 %0, {%1, %1};" : "=l"(r) : "r"(mi));
    return r;
}
__device__ __forceinline__ void unpack2(unsigned long long p, float& lo, float& hi) {
    unsigned int a, b;
    asm("mov.b64 {%0, %1}, %2;" : "=r"(a), "=r"(b) : "l"(p));
    lo = __uint_as_float(a);
    hi = __uint_as_float(b);
}

// ---------------- edge dtype detect ------------------------------------------
__global__ void detect_kernel(const int* __restrict__ w) {
    __shared__ int nonzero;
    if (threadIdx.x == 0) nonzero = 0;
    __syncthreads();
    int nz = 0;
    for (int i = threadIdx.x; i < 1024; i += 256)
        if (w[2 * i + 1] != 0) nz = 1;
    if (nz) nonzero = 1;              // benign race
    __syncthreads();
    if (threadIdx.x == 0) g_is64 = (nonzero == 0) ? 1 : 0;
}

__global__ void zero_cnt_kernel(int N) {
    int i = blockIdx.x * blockDim.x + threadIdx.x;
    if (i <= N) g_cnt[i] = 0;
}

// decode edges AND histogram dst in one pass
__global__ void convert_hist_kernel(const int* __restrict__ w, int E, int N) {
    int e = blockIdx.x * blockDim.x + threadIdx.x;
    if (e >= E) return;
    int s, d;
    if (g_is64) {
        s = w[2 * e];
        d = w[2 * (E + e)];
    } else {
        s = w[e];
        d = w[E + e];
    }
    s = min(max(s, 0), N - 1);        // clamp: never trap on bad data
    d = min(max(d, 0), N - 1);
    g_src[e] = s;
    g_dst[e] = d;
    atomicAdd(&g_cnt[d], 1);
}

// ---------------- multi-block exclusive scan ----------------------------------
// inclusive scan of 256 elems per block (warp shuffles + smem)
__device__ __forceinline__ int block_incl_scan(int v, int* wsum) {
    int lane = threadIdx.x & 31;
    int w = threadIdx.x >> 5;
    int x = v;
#pragma unroll
    for (int o = 1; o < 32; o <<= 1) {
        int y = __shfl_up_sync(0xffffffffu, x, o);
        if (lane >= o) x += y;
    }
    if (lane == 31) wsum[w] = x;
    __syncthreads();
    if (w == 0 && lane < 8) {
        int s = wsum[lane];
#pragma unroll
        for (int o = 1; o < 8; o <<= 1) {
            int y = __shfl_up_sync(0xffu, s, o);
            if (lane >= o) s += y;
        }
        wsum[lane] = s;
    }
    __syncthreads();
    return x + (w > 0 ? wsum[w - 1] : 0);
}

// phase 1: per-block exclusive scan of counts; block total to g_blksum
__global__ void __launch_bounds__(SCAN_BLK) scan_blk_kernel(int N) {
    __shared__ int wsum[8];
    int i = blockIdx.x * SCAN_BLK + threadIdx.x;
    int v = (i < N) ? g_cnt[i] : 0;
    int incl = block_incl_scan(v, wsum);
    if (i < N) g_rowptr[i] = incl - v;        // exclusive within block
    if (threadIdx.x == SCAN_BLK - 1) g_blksum[blockIdx.x] = incl;
}

// phase 2: single block scans NBLK block sums -> offsets; also rowptr[N] = E
__global__ void __launch_bounds__(SCAN_BLK) scan_top_kernel(int nblk, int N) {
    __shared__ int wsum[8];
    int b = threadIdx.x;
    int v = (b < nblk) ? g_blksum[b] : 0;
    int incl = block_incl_scan(v, wsum);
    if (b < nblk) g_blkoff[b] = incl - v;
    if (b == SCAN_BLK - 1) g_rowptr[N] = incl;   // grand total = E
}

// phase 3: add block offsets; init cursors
__global__ void __launch_bounds__(SCAN_BLK) scan_add_kernel(int N) {
    int i = blockIdx.x * SCAN_BLK + threadIdx.x;
    if (i < N) {
        int r = g_rowptr[i] + g_blkoff[blockIdx.x];
        g_rowptr[i] = r;
        g_cur[i] = r;
    }
}

__global__ void fill_kernel(int E) {
    int e = blockIdx.x * blockDim.x + threadIdx.x;
    if (e >= E) return;
    int pos = atomicAdd(&g_cur[g_dst[e]], 1);
    g_csr[pos] = g_src[e];
}

// ---------------- gather-mean aggregation ------------------------------------
__global__ void agg_mean128_kernel(const float* __restrict__ x, int N) {
    int warp = (int)(((size_t)blockIdx.x * blockDim.x + threadIdx.x) >> 5);
    int lane = threadIdx.x & 31;
    if (warp >= N) return;
    int beg = g_rowptr[warp];
    int end = g_rowptr[warp + 1];
    float4 acc0 = make_float4(0.f, 0.f, 0.f, 0.f);
    float4 acc1 = make_float4(0.f, 0.f, 0.f, 0.f);
    int i = beg;
    for (; i + 1 < end; i += 2) {
        int s0 = g_csr[i];
        int s1 = g_csr[i + 1];
        float4 v0 = reinterpret_cast<const float4*>(x + (size_t)s0 * 128)[lane];
        float4 v1 = reinterpret_cast<const float4*>(x + (size_t)s1 * 128)[lane];
        acc0.x += v0.x; acc0.y += v0.y; acc0.z += v0.z; acc0.w += v0.w;
        acc1.x += v1.x; acc1.y += v1.y; acc1.z += v1.z; acc1.w += v1.w;
    }
    if (i < end) {
        int s0 = g_csr[i];
        float4 v0 = reinterpret_cast<const float4*>(x + (size_t)s0 * 128)[lane];
        acc0.x += v0.x; acc0.y += v0.y; acc0.z += v0.z; acc0.w += v0.w;
    }
    int deg = end - beg;
    float rd = (deg > 0) ? (1.0f / (float)deg) : 0.0f;
    float4 r;
    r.x = (acc0.x + acc1.x) * rd;
    r.y = (acc0.y + acc1.y) * rd;
    r.z = (acc0.z + acc1.z) * rd;
    r.w = (acc0.w + acc1.w) * rd;
    reinterpret_cast<float4*>(g_aggm + (size_t)warp * 128)[lane] = r;
}

__global__ void agg_mean64_kernel(int N) {
    int warp = (int)(((size_t)blockIdx.x * blockDim.x + threadIdx.x) >> 5);
    int lane = threadIdx.x & 31;
    if (warp >= N) return;
    int beg = g_rowptr[warp];
    int end = g_rowptr[warp + 1];
    float2 acc0 = make_float2(0.f, 0.f);
    float2 acc1 = make_float2(0.f, 0.f);
    int i = beg;
    for (; i + 1 < end; i += 2) {
        int s0 = g_csr[i];
        int s1 = g_csr[i + 1];
        float2 v0 = reinterpret_cast<const float2*>(g_t2 + (size_t)s0 * 64)[lane];
        float2 v1 = reinterpret_cast<const float2*>(g_t2 + (size_t)s1 * 64)[lane];
        acc0.x += v0.x; acc0.y += v0.y;
        acc1.x += v1.x; acc1.y += v1.y;
    }
    if (i < end) {
        int s0 = g_csr[i];
        float2 v0 = reinterpret_cast<const float2*>(g_t2 + (size_t)s0 * 64)[lane];
        acc0.x += v0.x; acc0.y += v0.y;
    }
    int deg = end - beg;
    float rd = (deg > 0) ? (1.0f / (float)deg) : 0.0f;
    float2 r;
    r.x = (acc0.x + acc1.x) * rd;
    r.y = (acc0.y + acc1.y) * rd;
    reinterpret_cast<float2*>(g_aggm2 + (size_t)warp * 64)[lane] = r;
}

// ---------------- fused GEMM (K = 128, K-chunked, packed f32x2) ----------------
// MODE 1: g_h  = relu(g_aggm @ Wa + bias + Bx @ Wb)          (OUT=128, dual)
// MODE 2: g_t2 = g_h @ Wa                                     (OUT=64)
// MODE 3: outp = g_h @ Wa + bias + g_aggm2                    (OUT=64, side)
template<int MODE>
__global__ void __launch_bounds__(256)
sage_gemm(const float* __restrict__ Bx, const float* __restrict__ Wa,
          const float* __restrict__ Wb, const float* __restrict__ bias,
          float* __restrict__ outp, int nNodes) {
    constexpr int  OUT     = (MODE == 1) ? 128 : 64;
    constexpr bool DUAL    = (MODE == 1);
    constexpr bool RELU    = (MODE == 1);
    constexpr bool HASBIAS = (MODE != 2);
    constexpr bool SIDE    = (MODE == 3);
    constexpr int CT = OUT / 4;
    constexpr int GROUPS = 256 / CT;
    constexpr int TILE = GROUPS * 4;
    constexpr int KC = 32;
    constexpr int ASTR = KC + 4;

    __shared__ __align__(16) float Ws[KC * OUT];
    __shared__ __align__(16) float Wbs[DUAL ? KC * OUT : 4];
    __shared__ __align__(16) float As[TILE * ASTR];
    __shared__ __align__(16) float Bs[DUAL ? TILE * ASTR : 4];

    const float* A = (MODE == 1) ? g_aggm : g_h;
    float* op = (MODE == 1) ? g_h : ((MODE == 2) ? g_t2 : outp);

    const int cidx = threadIdx.x % CT;
    const int grp  = threadIdx.x / CT;
    const int c0   = cidx * 4;
    const int ln0  = grp * 4;

    int base = blockIdx.x * TILE;

    unsigned long long acc01[4] = {0ull, 0ull, 0ull, 0ull};
    unsigned long long acc23[4] = {0ull, 0ull, 0ull, 0ull};

    for (int ck = 0; ck < 4; ck++) {
        __syncthreads();
        for (int i = threadIdx.x; i < KC * OUT / 4; i += 256) {
            int row = i / (OUT / 4);
            int c4  = i % (OUT / 4);
            reinterpret_cast<float4*>(Ws)[row * (OUT / 4) + c4] =
                reinterpret_cast<const float4*>(Wa)[(ck * KC + row) * (OUT / 4) + c4];
        }
        if constexpr (DUAL) {
            for (int i = threadIdx.x; i < KC * OUT / 4; i += 256) {
                int row = i / (OUT / 4);
                int c4  = i % (OUT / 4);
                reinterpret_cast<float4*>(Wbs)[row * (OUT / 4) + c4] =
                    reinterpret_cast<const float4*>(Wb)[(ck * KC + row) * (OUT / 4) + c4];
            }
        }
        for (int i = threadIdx.x; i < TILE * (KC / 4); i += 256) {
            int r  = i / (KC / 4);
            int c4 = i % (KC / 4);
            int node = base + r;
            float4 v = make_float4(0.f, 0.f, 0.f, 0.f);
            if (node < nNodes)
                v = reinterpret_cast<const float4*>(A + (size_t)node * 128)[ck * (KC / 4) + c4];
            *reinterpret_cast<float4*>(As + r * ASTR + c4 * 4) = v;
        }
        if constexpr (DUAL) {
            for (int i = threadIdx.x; i < TILE * (KC / 4); i += 256) {
                int r  = i / (KC / 4);
                int c4 = i % (KC / 4);
                int node = base + r;
                float4 v = make_float4(0.f, 0.f, 0.f, 0.f);
                if (node < nNodes)
                    v = reinterpret_cast<const float4*>(Bx + (size_t)node * 128)[ck * (KC / 4) + c4];
                *reinterpret_cast<float4*>(Bs + r * ASTR + c4 * 4) = v;
            }
        }
        __syncthreads();

#pragma unroll 4
        for (int k = 0; k < KC; k++) {
            ulonglong2 w = *reinterpret_cast<const ulonglong2*>(Ws + k * OUT + c0);
            {
                unsigned long long m;
                m = pack2(As[(ln0 + 0) * ASTR + k]); fma2(acc01[0], w.x, m); fma2(acc23[0], w.y, m);
                m = pack2(As[(ln0 + 1) * ASTR + k]); fma2(acc01[1], w.x, m); fma2(acc23[1], w.y, m);
                m = pack2(As[(ln0 + 2) * ASTR + k]); fma2(acc01[2], w.x, m); fma2(acc23[2], w.y, m);
                m = pack2(As[(ln0 + 3) * ASTR + k]); fma2(acc01[3], w.x, m); fma2(acc23[3], w.y, m);
            }
            if constexpr (DUAL) {
                ulonglong2 w2 = *reinterpret_cast<const ulonglong2*>(Wbs + k * OUT + c0);
                unsigned long long m;
                m = pack2(Bs[(ln0 + 0) * ASTR + k]); fma2(acc01[0], w2.x, m); fma2(acc23[0], w2.y, m);
                m = pack2(Bs[(ln0 + 1) * ASTR + k]); fma2(acc01[1], w2.x, m); fma2(acc23[1], w2.y, m);
                m = pack2(Bs[(ln0 + 2) * ASTR + k]); fma2(acc01[2], w2.x, m); fma2(acc23[2], w2.y, m);
                m = pack2(Bs[(ln0 + 3) * ASTR + k]); fma2(acc01[3], w2.x, m); fma2(acc23[3], w2.y, m);
            }
        }
    }

    float4 bv = make_float4(0.f, 0.f, 0.f, 0.f);
    if constexpr (HASBIAS) bv = reinterpret_cast<const float4*>(bias)[cidx];

#pragma unroll
    for (int n = 0; n < 4; n++) {
        int node = base + ln0 + n;
        if (node >= nNodes) continue;
        float r0, r1, r2, r3;
        unpack2(acc01[n], r0, r1);
        unpack2(acc23[n], r2, r3);
        if constexpr (HASBIAS) { r0 += bv.x; r1 += bv.y; r2 += bv.z; r3 += bv.w; }
        if constexpr (SIDE) {
            float4 sv = *reinterpret_cast<const float4*>(g_aggm2 + (size_t)node * 64 + c0);
            r0 += sv.x; r1 += sv.y; r2 += sv.z; r3 += sv.w;
        }
        if constexpr (RELU) {
            r0 = fmaxf(r0, 0.f); r1 = fmaxf(r1, 0.f);
            r2 = fmaxf(r2, 0.f); r3 = fmaxf(r3, 0.f);
        }
        *reinterpret_cast<float4*>(op + (size_t)node * OUT + c0) =
            make_float4(r0, r1, r2, r3);
    }
}

// ---------------- launch -------------------------------------------------------
extern "C" void kernel_launch(void* const* d_in, const int* in_sizes, int n_in,
                              void* d_out, int out_size) {
    const float* x       = (const float*)d_in[0];
    const int*   ei_w    = (const int*)d_in[1];
    const float* W1l     = (const float*)d_in[2];
    const float* b1      = (const float*)d_in[3];
    const float* W1r     = (const float*)d_in[4];
    const float* W2l     = (const float*)d_in[5];
    const float* b2      = (const float*)d_in[6];
    const float* W2r     = (const float*)d_in[7];
    float* out = (float*)d_out;

    int N = in_sizes[0] / 128;
    int E = in_sizes[1] / 2;
    int nblk = (N + SCAN_BLK - 1) / SCAN_BLK;

    // --- decode + CSR build (int atomics only) ---
    detect_kernel<<<1, 256>>>(ei_w);
    zero_cnt_kernel<<<(N + 256) / 256, 256>>>(N);
    convert_hist_kernel<<<(E + 255) / 256, 256>>>(ei_w, E, N);
    scan_blk_kernel<<<nblk, SCAN_BLK>>>(N);
    scan_top_kernel<<<1, SCAN_BLK>>>(nblk, N);
    scan_add_kernel<<<nblk, SCAN_BLK>>>(N);
    fill_kernel<<<(E + 255) / 256, 256>>>(E);

    // --- layer 1: mean-gather then dual GEMM ---
    {
        size_t threads = (size_t)N * 32;
        agg_mean128_kernel<<<(int)((threads + 255) / 256), 256>>>(x, N);
    }
    sage_gemm<1><<<(N + 31) / 32, 256>>>(x, W1l, W1r, b1, nullptr, N);

    // --- layer 2: transform, mean-gather, final GEMM ---
    sage_gemm<2><<<(N + 63) / 64, 256>>>(nullptr, W2l, nullptr, nullptr, nullptr, N);
    {
        size_t threads = (size_t)N * 32;
        agg_mean64_kernel<<<(int)((threads + 255) / 256), 256>>>(N);
    }
    sage_gemm<3><<<(N + 63) / 64, 256>>>(nullptr, W2r, nullptr, b2, out, N);
}

// round 7
// speedup vs baseline: 1.3512x; 1.0189x over previous
#include <cuda_runtime.h>
#include <cstdint>

#define MAXN 50176
#define MAXE 800000
#define SCAN_BLK 256
#define NBLK ((MAXN + SCAN_BLK - 1) / SCAN_BLK)   // 196

// ---------------- scratch (device globals; no allocation allowed) -----------
__device__ int   g_is64;                           // edge dtype flag
__device__ int   g_src[MAXE];                      // decoded src ids (int32)
__device__ int   g_dst[MAXE];                      // decoded dst ids (int32)
__device__ int   g_cnt[MAXN + 1];                  // histogram
__device__ int   g_rowptr[MAXN + 1];               // CSR row pointers
__device__ int   g_cur[MAXN + 1];                  // fill cursors
__device__ int   g_csr[MAXE];                      // src ids grouped by dst
__device__ int   g_blksum[NBLK];                   // scan phase-1 block sums
__device__ int   g_blkoff[NBLK];                   // scan phase-2 block offsets
__device__ float g_aggm[(size_t)MAXN * 128];       // layer-1 mean aggregation
__device__ float g_h[(size_t)MAXN * 128];          // layer-1 output
__device__ float g_t2[(size_t)MAXN * 64];          // h @ W2l
__device__ float g_aggm2[(size_t)MAXN * 64];       // layer-2 mean aggregation

// ---------------- packed f32x2 helpers ---------------------------------------
__device__ __forceinline__ void fma2(unsigned long long& acc,
                                     unsigned long long a,
                                     unsigned long long b) {
    asm("fma.rn.f32x2 %0, %1, %2, %0;" : "+l"(acc) : "l"(a), "l"(b));
}
__device__ __forceinline__ unsigned long long pack2(float m) {
    unsigned long long r;
    unsigned int mi = __float_as_uint(m);
    asm("mov.b64 %0, {%1, %1};" : "=l"(r) : "r"(mi));
    return r;
}
__device__ __forceinline__ void unpack2(unsigned long long p, float& lo, float& hi) {
    unsigned int a, b;
    asm("mov.b64 {%0, %1}, %2;" : "=r"(a), "=r"(b) : "l"(p));
    lo = __uint_as_float(a);
    hi = __uint_as_float(b);
}

// ---------------- edge dtype detect ------------------------------------------
__global__ void detect_kernel(const int* __restrict__ w) {
    __shared__ int nonzero;
    if (threadIdx.x == 0) nonzero = 0;
    __syncthreads();
    int nz = 0;
    for (int i = threadIdx.x; i < 1024; i += 256)
        if (w[2 * i + 1] != 0) nz = 1;
    if (nz) nonzero = 1;              // benign race
    __syncthreads();
    if (threadIdx.x == 0) g_is64 = (nonzero == 0) ? 1 : 0;
}

__global__ void zero_cnt_kernel(int N) {
    int i = blockIdx.x * blockDim.x + threadIdx.x;
    if (i <= N) g_cnt[i] = 0;
}

// decode edges AND histogram dst in one pass
__global__ void convert_hist_kernel(const int* __restrict__ w, int E, int N) {
    int e = blockIdx.x * blockDim.x + threadIdx.x;
    if (e >= E) return;
    int s, d;
    if (g_is64) {
        s = w[2 * e];
        d = w[2 * (E + e)];
    } else {
        s = w[e];
        d = w[E + e];
    }
    s = min(max(s, 0), N - 1);        // clamp: never trap on bad data
    d = min(max(d, 0), N - 1);
    g_src[e] = s;
    g_dst[e] = d;
    atomicAdd(&g_cnt[d], 1);
}

// ---------------- multi-block exclusive scan ----------------------------------
__device__ __forceinline__ int block_incl_scan(int v, int* wsum) {
    int lane = threadIdx.x & 31;
    int w = threadIdx.x >> 5;
    int x = v;
#pragma unroll
    for (int o = 1; o < 32; o <<= 1) {
        int y = __shfl_up_sync(0xffffffffu, x, o);
        if (lane >= o) x += y;
    }
    if (lane == 31) wsum[w] = x;
    __syncthreads();
    if (w == 0 && lane < 8) {
        int s = wsum[lane];
#pragma unroll
        for (int o = 1; o < 8; o <<= 1) {
            int y = __shfl_up_sync(0xffu, s, o);
            if (lane >= o) s += y;
        }
        wsum[lane] = s;
    }
    __syncthreads();
    return x + (w > 0 ? wsum[w - 1] : 0);
}

__global__ void __launch_bounds__(SCAN_BLK) scan_blk_kernel(int N) {
    __shared__ int wsum[8];
    int i = blockIdx.x * SCAN_BLK + threadIdx.x;
    int v = (i < N) ? g_cnt[i] : 0;
    int incl = block_incl_scan(v, wsum);
    if (i < N) g_rowptr[i] = incl - v;
    if (threadIdx.x == SCAN_BLK - 1) g_blksum[blockIdx.x] = incl;
}

__global__ void __launch_bounds__(SCAN_BLK) scan_top_kernel(int nblk, int N) {
    __shared__ int wsum[8];
    int b = threadIdx.x;
    int v = (b < nblk) ? g_blksum[b] : 0;
    int incl = block_incl_scan(v, wsum);
    if (b < nblk) g_blkoff[b] = incl - v;
    if (b == SCAN_BLK - 1) g_rowptr[N] = incl;
}

__global__ void __launch_bounds__(SCAN_BLK) scan_add_kernel(int N) {
    int i = blockIdx.x * SCAN_BLK + threadIdx.x;
    if (i < N) {
        int r = g_rowptr[i] + g_blkoff[blockIdx.x];
        g_rowptr[i] = r;
        g_cur[i] = r;
    }
}

__global__ void fill_kernel(int E) {
    int e = blockIdx.x * blockDim.x + threadIdx.x;
    if (e >= E) return;
    int pos = atomicAdd(&g_cur[g_dst[e]], 1);
    g_csr[pos] = g_src[e];
}

// ---------------- gather-mean aggregation ------------------------------------
__global__ void agg_mean128_kernel(const float* __restrict__ x, int N) {
    int warp = (int)(((size_t)blockIdx.x * blockDim.x + threadIdx.x) >> 5);
    int lane = threadIdx.x & 31;
    if (warp >= N) return;
    int beg = g_rowptr[warp];
    int end = g_rowptr[warp + 1];
    float4 acc0 = make_float4(0.f, 0.f, 0.f, 0.f);
    float4 acc1 = make_float4(0.f, 0.f, 0.f, 0.f);
    int i = beg;
    for (; i + 1 < end; i += 2) {
        int s0 = g_csr[i];
        int s1 = g_csr[i + 1];
        float4 v0 = reinterpret_cast<const float4*>(x + (size_t)s0 * 128)[lane];
        float4 v1 = reinterpret_cast<const float4*>(x + (size_t)s1 * 128)[lane];
        acc0.x += v0.x; acc0.y += v0.y; acc0.z += v0.z; acc0.w += v0.w;
        acc1.x += v1.x; acc1.y += v1.y; acc1.z += v1.z; acc1.w += v1.w;
    }
    if (i < end) {
        int s0 = g_csr[i];
        float4 v0 = reinterpret_cast<const float4*>(x + (size_t)s0 * 128)[lane];
        acc0.x += v0.x; acc0.y += v0.y; acc0.z += v0.z; acc0.w += v0.w;
    }
    int deg = end - beg;
    float rd = (deg > 0) ? (1.0f / (float)deg) : 0.0f;
    float4 r;
    r.x = (acc0.x + acc1.x) * rd;
    r.y = (acc0.y + acc1.y) * rd;
    r.z = (acc0.z + acc1.z) * rd;
    r.w = (acc0.w + acc1.w) * rd;
    reinterpret_cast<float4*>(g_aggm + (size_t)warp * 128)[lane] = r;
}

__global__ void agg_mean64_kernel(int N) {
    int warp = (int)(((size_t)blockIdx.x * blockDim.x + threadIdx.x) >> 5);
    int lane = threadIdx.x & 31;
    if (warp >= N) return;
    int beg = g_rowptr[warp];
    int end = g_rowptr[warp + 1];
    float2 acc0 = make_float2(0.f, 0.f);
    float2 acc1 = make_float2(0.f, 0.f);
    int i = beg;
    for (; i + 1 < end; i += 2) {
        int s0 = g_csr[i];
        int s1 = g_csr[i + 1];
        float2 v0 = reinterpret_cast<const float2*>(g_t2 + (size_t)s0 * 64)[lane];
        float2 v1 = reinterpret_cast<const float2*>(g_t2 + (size_t)s1 * 64)[lane];
        acc0.x += v0.x; acc0.y += v0.y;
        acc1.x += v1.x; acc1.y += v1.y;
    }
    if (i < end) {
        int s0 = g_csr[i];
        float2 v0 = reinterpret_cast<const float2*>(g_t2 + (size_t)s0 * 64)[lane];
        acc0.x += v0.x; acc0.y += v0.y;
    }
    int deg = end - beg;
    float rd = (deg > 0) ? (1.0f / (float)deg) : 0.0f;
    float2 r;
    r.x = (acc0.x + acc1.x) * rd;
    r.y = (acc0.y + acc1.y) * rd;
    reinterpret_cast<float2*>(g_aggm2 + (size_t)warp * 64)[lane] = r;
}

// ---------------- fused layer-1 GEMM + layer-2 transform ----------------------
// Phase 1: h = relu(g_aggm @ W1l + b1 + x @ W1r)   [64-node tile, OUT=128]
// Phase 2: t2 = h @ W2l                            (h tile reused from smem)
// 256 threads. Phase 1: 32 col-threads x 8 groups x 8 nodes. KC=16 chunks.
__global__ void __launch_bounds__(256)
gemm1_fused(const float* __restrict__ x, const float* __restrict__ W1l,
            const float* __restrict__ W1r, const float* __restrict__ b1,
            const float* __restrict__ W2l, int nNodes) {
    constexpr int TILE = 64;
    constexpr int KC = 16;
    constexpr int ASTR = KC + 4;      // 20
    constexpr int HSTR = 132;

    // phase-1 buffers alias phase-2 buffers
    __shared__ __align__(16) float smem[9728];  // 38912 B
    float* Ws  = smem;                 // [KC*128] 8KB
    float* Wbs = smem + KC * 128;      // [KC*128] 8KB
    float* As  = smem + 2 * KC * 128;  // [64*20] 5KB
    float* Bs  = As + TILE * ASTR;     // [64*20] 5KB
    float* Hs  = smem;                 // phase 2: [64*132] 33.8KB
    float* W2s = smem + TILE * HSTR;   // phase 2: [KC*64] 4KB

    const int tid  = threadIdx.x;
    const int cidx = tid & 31;         // 32 col-threads
    const int grp  = tid >> 5;         // 8 groups
    const int c0   = cidx * 4;
    const int ln0  = grp * 8;          // 8 nodes per group

    const int base = blockIdx.x * TILE;

    unsigned long long acc01[8], acc23[8];
#pragma unroll
    for (int n = 0; n < 8; n++) { acc01[n] = 0ull; acc23[n] = 0ull; }

    for (int ck = 0; ck < 8; ck++) {
        __syncthreads();
        // stage weight chunks [KC x 128]
        for (int i = tid; i < KC * 32; i += 256) {
            reinterpret_cast<float4*>(Ws)[i] =
                reinterpret_cast<const float4*>(W1l)[ck * KC * 32 + i];
            reinterpret_cast<float4*>(Wbs)[i] =
                reinterpret_cast<const float4*>(W1r)[ck * KC * 32 + i];
        }
        // stage A/B tiles [64 x KC] (1 float4 per thread each)
        {
            int r  = tid >> 2;         // 0..63
            int c4 = tid & 3;          // 0..3
            int node = base + r;
            float4 va = make_float4(0.f, 0.f, 0.f, 0.f);
            float4 vb = make_float4(0.f, 0.f, 0.f, 0.f);
            if (node < nNodes) {
                va = reinterpret_cast<const float4*>(g_aggm + (size_t)node * 128)[ck * 4 + c4];
                vb = reinterpret_cast<const float4*>(x + (size_t)node * 128)[ck * 4 + c4];
            }
            *reinterpret_cast<float4*>(As + r * ASTR + c4 * 4) = va;
            *reinterpret_cast<float4*>(Bs + r * ASTR + c4 * 4) = vb;
        }
        __syncthreads();

#pragma unroll 4
        for (int k = 0; k < KC; k++) {
            ulonglong2 w  = *reinterpret_cast<const ulonglong2*>(Ws + k * 128 + c0);
            ulonglong2 w2 = *reinterpret_cast<const ulonglong2*>(Wbs + k * 128 + c0);
#pragma unroll
            for (int n = 0; n < 8; n++) {
                unsigned long long m = pack2(As[(ln0 + n) * ASTR + k]);
                fma2(acc01[n], w.x, m);
                fma2(acc23[n], w.y, m);
            }
#pragma unroll
            for (int n = 0; n < 8; n++) {
                unsigned long long m = pack2(Bs[(ln0 + n) * ASTR + k]);
                fma2(acc01[n], w2.x, m);
                fma2(acc23[n], w2.y, m);
            }
        }
    }

    // phase-1 epilogue: relu(+bias), write h to global AND to Hs (aliases Ws/As)
    float4 bv = reinterpret_cast<const float4*>(b1)[cidx];
    __syncthreads();   // everyone done reading As/Ws before Hs overwrite
#pragma unroll
    for (int n = 0; n < 8; n++) {
        float r0, r1, r2, r3;
        unpack2(acc01[n], r0, r1);
        unpack2(acc23[n], r2, r3);
        r0 = fmaxf(r0 + bv.x, 0.f);
        r1 = fmaxf(r1 + bv.y, 0.f);
        r2 = fmaxf(r2 + bv.z, 0.f);
        r3 = fmaxf(r3 + bv.w, 0.f);
        float4 hv = make_float4(r0, r1, r2, r3);
        *reinterpret_cast<float4*>(Hs + (ln0 + n) * HSTR + c0) = hv;
        int node = base + ln0 + n;
        if (node < nNodes)
            *reinterpret_cast<float4*>(g_h + (size_t)node * 128 + c0) = hv;
    }

    // ---- phase 2: t2 = h @ W2l  (OUT=64) ----
    const int cidx2 = tid & 15;        // 16 col-threads (64 cols)
    const int grp2  = tid >> 4;        // 16 groups x 4 nodes
    const int c0b   = cidx2 * 4;
    const int lnb   = grp2 * 4;

    unsigned long long a01[4] = {0ull, 0ull, 0ull, 0ull};
    unsigned long long a23[4] = {0ull, 0ull, 0ull, 0ull};

    for (int ck = 0; ck < 8; ck++) {
        __syncthreads();
        // stage W2l chunk [KC x 64]: 256 float4 -> 1 per thread
        reinterpret_cast<float4*>(W2s)[tid] =
            reinterpret_cast<const float4*>(W2l)[ck * KC * 16 + tid];
        __syncthreads();
#pragma unroll 4
        for (int k = 0; k < KC; k++) {
            ulonglong2 w = *reinterpret_cast<const ulonglong2*>(W2s + k * 64 + c0b);
#pragma unroll
            for (int n = 0; n < 4; n++) {
                unsigned long long m = pack2(Hs[(lnb + n) * HSTR + ck * KC + k]);
                fma2(a01[n], w.x, m);
                fma2(a23[n], w.y, m);
            }
        }
    }

#pragma unroll
    for (int n = 0; n < 4; n++) {
        int node = base + lnb + n;
        if (node >= nNodes) continue;
        float r0, r1, r2, r3;
        unpack2(a01[n], r0, r1);
        unpack2(a23[n], r2, r3);
        *reinterpret_cast<float4*>(g_t2 + (size_t)node * 64 + c0b) =
            make_float4(r0, r1, r2, r3);
    }
}

// ---------------- final GEMM: out = h @ W2r + b2 + aggm2 -----------------------
__global__ void __launch_bounds__(256)
gemm3_kernel(const float* __restrict__ W2r, const float* __restrict__ b2,
             float* __restrict__ outp, int nNodes) {
    constexpr int OUT = 64;
    constexpr int CT = 16;
    constexpr int TILE = 64;
    constexpr int KC = 32;
    constexpr int ASTR = KC + 4;

    __shared__ __align__(16) float Ws[KC * OUT];
    __shared__ __align__(16) float As[TILE * ASTR];

    const int tid  = threadIdx.x;
    const int cidx = tid % CT;
    const int grp  = tid / CT;
    const int c0   = cidx * 4;
    const int ln0  = grp * 4;

    int base = blockIdx.x * TILE;

    unsigned long long acc01[4] = {0ull, 0ull, 0ull, 0ull};
    unsigned long long acc23[4] = {0ull, 0ull, 0ull, 0ull};

    for (int ck = 0; ck < 4; ck++) {
        __syncthreads();
        for (int i = tid; i < KC * OUT / 4; i += 256)
            reinterpret_cast<float4*>(Ws)[i] =
                reinterpret_cast<const float4*>(W2r)[ck * KC * OUT / 4 + i];
        for (int i = tid; i < TILE * (KC / 4); i += 256) {
            int r  = i / (KC / 4);
            int c4 = i % (KC / 4);
            int node = base + r;
            float4 v = make_float4(0.f, 0.f, 0.f, 0.f);
            if (node < nNodes)
                v = reinterpret_cast<const float4*>(g_h + (size_t)node * 128)[ck * (KC / 4) + c4];
            *reinterpret_cast<float4*>(As + r * ASTR + c4 * 4) = v;
        }
        __syncthreads();

#pragma unroll 4
        for (int k = 0; k < KC; k++) {
            ulonglong2 w = *reinterpret_cast<const ulonglong2*>(Ws + k * OUT + c0);
#pragma unroll
            for (int n = 0; n < 4; n++) {
                unsigned long long m = pack2(As[(ln0 + n) * ASTR + k]);
                fma2(acc01[n], w.x, m);
                fma2(acc23[n], w.y, m);
            }
        }
    }

    float4 bv = reinterpret_cast<const float4*>(b2)[cidx];
#pragma unroll
    for (int n = 0; n < 4; n++) {
        int node = base + ln0 + n;
        if (node >= nNodes) continue;
        float r0, r1, r2, r3;
        unpack2(acc01[n], r0, r1);
        unpack2(acc23[n], r2, r3);
        float4 sv = *reinterpret_cast<const float4*>(g_aggm2 + (size_t)node * 64 + c0);
        r0 += bv.x + sv.x;
        r1 += bv.y + sv.y;
        r2 += bv.z + sv.z;
        r3 += bv.w + sv.w;
        *reinterpret_cast<float4*>(outp + (size_t)node * 64 + c0) =
            make_float4(r0, r1, r2, r3);
    }
}

// ---------------- launch -------------------------------------------------------
extern "C" void kernel_launch(void* const* d_in, const int* in_sizes, int n_in,
                              void* d_out, int out_size) {
    const float* x       = (const float*)d_in[0];
    const int*   ei_w    = (const int*)d_in[1];
    const float* W1l     = (const float*)d_in[2];
    const float* b1      = (const float*)d_in[3];
    const float* W1r     = (const float*)d_in[4];
    const float* W2l     = (const float*)d_in[5];
    const float* b2      = (const float*)d_in[6];
    const float* W2r     = (const float*)d_in[7];
    float* out = (float*)d_out;

    int N = in_sizes[0] / 128;
    int E = in_sizes[1] / 2;
    int nblk = (N + SCAN_BLK - 1) / SCAN_BLK;

    // --- decode + CSR build (int atomics only) ---
    detect_kernel<<<1, 256>>>(ei_w);
    zero_cnt_kernel<<<(N + 256) / 256, 256>>>(N);
    convert_hist_kernel<<<(E + 255) / 256, 256>>>(ei_w, E, N);
    scan_blk_kernel<<<nblk, SCAN_BLK>>>(N);
    scan_top_kernel<<<1, SCAN_BLK>>>(nblk, N);
    scan_add_kernel<<<nblk, SCAN_BLK>>>(N);
    fill_kernel<<<(E + 255) / 256, 256>>>(E);

    // --- layer 1 (+ layer-2 transform fused) ---
    {
        size_t threads = (size_t)N * 32;
        agg_mean128_kernel<<<(int)((threads + 255) / 256), 256>>>(x, N);
    }
    gemm1_fused<<<(N + 63) / 64, 256>>>(x, W1l, W1r, b1, W2l, N);

    // --- layer 2: mean-gather of t2, final GEMM ---
    {
        size_t threads = (size_t)N * 32;
        agg_mean64_kernel<<<(int)((threads + 255) / 256), 256>>>(N);
    }
    gemm3_kernel<<<(N + 63) / 64, 256>>>(W2r, b2, out, N);
}

// round 9
// speedup vs baseline: 1.5513x; 1.1481x over previous
#include <cuda_runtime.h>
#include <mma.h>
#include <cstdint>

using namespace nvcuda;

#define MAXN 50176
#define MAXE 800000
#define SCAN_BLK 256
#define NBLK ((MAXN + SCAN_BLK - 1) / SCAN_BLK)   // 196

// ---------------- scratch (device globals; no allocation allowed) -----------
__device__ int   g_is64;                           // edge dtype flag
__device__ int   g_src[MAXE];                      // decoded src ids (int32)
__device__ int   g_dst[MAXE];                      // decoded dst ids (int32)
__device__ int   g_cnt[MAXN + 1];                  // histogram
__device__ int   g_rowptr[MAXN + 1];               // CSR row pointers
__device__ int   g_cur[MAXN + 1];                  // fill cursors
__device__ int   g_csr[MAXE];                      // src ids grouped by dst
__device__ int   g_blksum[NBLK];                   // scan phase-1 block sums
__device__ int   g_blkoff[NBLK];                   // scan phase-2 block offsets
__device__ float g_aggm[(size_t)MAXN * 128];       // layer-1 mean aggregation
__device__ float g_h[(size_t)MAXN * 128];          // layer-1 output (padded)
__device__ float g_t2[(size_t)MAXN * 64];          // h @ W2l (padded)
__device__ float g_aggm2[(size_t)MAXN * 64];       // layer-2 mean aggregation

// ---------------- edge dtype detect ------------------------------------------
__global__ void detect_kernel(const int* __restrict__ w) {
    __shared__ int nonzero;
    if (threadIdx.x == 0) nonzero = 0;
    __syncthreads();
    int nz = 0;
    for (int i = threadIdx.x; i < 1024; i += 256)
        if (w[2 * i + 1] != 0) nz = 1;
    if (nz) nonzero = 1;              // benign race
    __syncthreads();
    if (threadIdx.x == 0) g_is64 = (nonzero == 0) ? 1 : 0;
}

__global__ void zero_cnt_kernel(int N) {
    int i = blockIdx.x * blockDim.x + threadIdx.x;
    if (i <= N) g_cnt[i] = 0;
}

// decode edges AND histogram dst in one pass
__global__ void convert_hist_kernel(const int* __restrict__ w, int E, int N) {
    int e = blockIdx.x * blockDim.x + threadIdx.x;
    if (e >= E) return;
    int s, d;
    if (g_is64) {
        s = w[2 * e];
        d = w[2 * (E + e)];
    } else {
        s = w[e];
        d = w[E + e];
    }
    s = min(max(s, 0), N - 1);        // clamp: never trap on bad data
    d = min(max(d, 0), N - 1);
    g_src[e] = s;
    g_dst[e] = d;
    atomicAdd(&g_cnt[d], 1);
}

// ---------------- multi-block exclusive scan ----------------------------------
__device__ __forceinline__ int block_incl_scan(int v, int* wsum) {
    int lane = threadIdx.x & 31;
    int w = threadIdx.x >> 5;
    int x = v;
#pragma unroll
    for (int o = 1; o < 32; o <<= 1) {
        int y = __shfl_up_sync(0xffffffffu, x, o);
        if (lane >= o) x += y;
    }
    if (lane == 31) wsum[w] = x;
    __syncthreads();
    if (w == 0 && lane < 8) {
        int s = wsum[lane];
#pragma unroll
        for (int o = 1; o < 8; o <<= 1) {
            int y = __shfl_up_sync(0xffu, s, o);
            if (lane >= o) s += y;
        }
        wsum[lane] = s;
    }
    __syncthreads();
    return x + (w > 0 ? wsum[w - 1] : 0);
}

__global__ void __launch_bounds__(SCAN_BLK) scan_blk_kernel(int N) {
    __shared__ int wsum[8];
    int i = blockIdx.x * SCAN_BLK + threadIdx.x;
    int v = (i < N) ? g_cnt[i] : 0;
    int incl = block_incl_scan(v, wsum);
    if (i < N) g_rowptr[i] = incl - v;
    if (threadIdx.x == SCAN_BLK - 1) g_blksum[blockIdx.x] = incl;
}

__global__ void __launch_bounds__(SCAN_BLK) scan_top_kernel(int nblk, int N) {
    __shared__ int wsum[8];
    int b = threadIdx.x;
    int v = (b < nblk) ? g_blksum[b] : 0;
    int incl = block_incl_scan(v, wsum);
    if (b < nblk) g_blkoff[b] = incl - v;
    if (b == SCAN_BLK - 1) g_rowptr[N] = incl;
}

__global__ void __launch_bounds__(SCAN_BLK) scan_add_kernel(int N) {
    int i = blockIdx.x * SCAN_BLK + threadIdx.x;
    if (i < N) {
        int r = g_rowptr[i] + g_blkoff[blockIdx.x];
        g_rowptr[i] = r;
        g_cur[i] = r;
    }
}

__global__ void fill_kernel(int E) {
    int e = blockIdx.x * blockDim.x + threadIdx.x;
    if (e >= E) return;
    int pos = atomicAdd(&g_cur[g_dst[e]], 1);
    g_csr[pos] = g_src[e];
}

// ---------------- gather-mean aggregation ------------------------------------
__global__ void agg_mean128_kernel(const float* __restrict__ x, int N) {
    int warp = (int)(((size_t)blockIdx.x * blockDim.x + threadIdx.x) >> 5);
    int lane = threadIdx.x & 31;
    if (warp >= N) return;
    int beg = g_rowptr[warp];
    int end = g_rowptr[warp + 1];
    float4 acc0 = make_float4(0.f, 0.f, 0.f, 0.f);
    float4 acc1 = make_float4(0.f, 0.f, 0.f, 0.f);
    int i = beg;
    for (; i + 1 < end; i += 2) {
        int s0 = g_csr[i];
        int s1 = g_csr[i + 1];
        float4 v0 = reinterpret_cast<const float4*>(x + (size_t)s0 * 128)[lane];
        float4 v1 = reinterpret_cast<const float4*>(x + (size_t)s1 * 128)[lane];
        acc0.x += v0.x; acc0.y += v0.y; acc0.z += v0.z; acc0.w += v0.w;
        acc1.x += v1.x; acc1.y += v1.y; acc1.z += v1.z; acc1.w += v1.w;
    }
    if (i < end) {
        int s0 = g_csr[i];
        float4 v0 = reinterpret_cast<const float4*>(x + (size_t)s0 * 128)[lane];
        acc0.x += v0.x; acc0.y += v0.y; acc0.z += v0.z; acc0.w += v0.w;
    }
    int deg = end - beg;
    float rd = (deg > 0) ? (1.0f / (float)deg) : 0.0f;
    float4 r;
    r.x = (acc0.x + acc1.x) * rd;
    r.y = (acc0.y + acc1.y) * rd;
    r.z = (acc0.z + acc1.z) * rd;
    r.w = (acc0.w + acc1.w) * rd;
    reinterpret_cast<float4*>(g_aggm + (size_t)warp * 128)[lane] = r;
}

__global__ void agg_mean64_kernel(int N) {
    int warp = (int)(((size_t)blockIdx.x * blockDim.x + threadIdx.x) >> 5);
    int lane = threadIdx.x & 31;
    if (warp >= N) return;
    int beg = g_rowptr[warp];
    int end = g_rowptr[warp + 1];
    float2 acc0 = make_float2(0.f, 0.f);
    float2 acc1 = make_float2(0.f, 0.f);
    int i = beg;
    for (; i + 1 < end; i += 2) {
        int s0 = g_csr[i];
        int s1 = g_csr[i + 1];
        float2 v0 = reinterpret_cast<const float2*>(g_t2 + (size_t)s0 * 64)[lane];
        float2 v1 = reinterpret_cast<const float2*>(g_t2 + (size_t)s1 * 64)[lane];
        acc0.x += v0.x; acc0.y += v0.y;
        acc1.x += v1.x; acc1.y += v1.y;
    }
    if (i < end) {
        int s0 = g_csr[i];
        float2 v0 = reinterpret_cast<const float2*>(g_t2 + (size_t)s0 * 64)[lane];
        acc0.x += v0.x; acc0.y += v0.y;
    }
    int deg = end - beg;
    float rd = (deg > 0) ? (1.0f / (float)deg) : 0.0f;
    float2 r;
    r.x = (acc0.x + acc1.x) * rd;
    r.y = (acc0.y + acc1.y) * rd;
    reinterpret_cast<float2*>(g_aggm2 + (size_t)warp * 64)[lane] = r;
}

// ---------------- WMMA helpers -------------------------------------------------
using FragA = wmma::fragment<wmma::matrix_a, 16, 16, 8, wmma::precision::tf32, wmma::row_major>;
using FragB = wmma::fragment<wmma::matrix_b, 16, 16, 8, wmma::precision::tf32, wmma::row_major>;
using FragC = wmma::fragment<wmma::accumulator, 16, 16, 8, float>;

__device__ __forceinline__ void cvt_tf32(FragA& f) {
#pragma unroll
    for (int i = 0; i < f.num_elements; i++) f.x[i] = wmma::__float_to_tf32(f.x[i]);
}
__device__ __forceinline__ void cvt_tf32(FragB& f) {
#pragma unroll
    for (int i = 0; i < f.num_elements; i++) f.x[i] = wmma::__float_to_tf32(f.x[i]);
}

// ---------------- fused layer-1 GEMM + layer-2 transform (WMMA tf32) -----------
// Phase 1: h  = relu(g_aggm @ W1l + x @ W1r + b1)   [64 nodes x 128]
// Phase 2: t2 = h @ W2l                              [64 nodes x 64]
__global__ void __launch_bounds__(256)
gemm1_fused(const float* __restrict__ x, const float* __restrict__ W1l,
            const float* __restrict__ W1r, const float* __restrict__ b1,
            const float* __restrict__ W2l, int nNodes) {
    constexpr int WSTR = 132;   // Ws row stride (128 cols)
    constexpr int ASTR = 36;    // As row stride (32 cols)
    constexpr int HSTR = 132;   // Hs row stride (128 cols)
    constexpr int W2STR = 68;   // W2s row stride (64 cols)

    __shared__ __align__(16) float smem[10624];   // 42496 B
    float* Ws  = smem;                 // [32 x WSTR]  phase 1 (0..4224)
    float* As  = smem + 32 * WSTR;     // [64 x ASTR]  phase 1 (4224..6528)
    float* Hs  = smem;                 // [64 x HSTR]  phase 1 epi + phase 2 (0..8448)
    float* W2s = smem + 64 * HSTR;     // [32 x W2STR] phase 2 (8448..10624)

    const int tid = threadIdx.x;
    const int wid = tid >> 5;
    const int wr  = wid >> 1;          // 4 row chunks of 16 nodes
    const int wc  = wid & 1;           // 2 col halves of 64

    const int base = blockIdx.x * 64;

    FragC acc[4];
#pragma unroll
    for (int j = 0; j < 4; j++) wmma::fill_fragment(acc[j], 0.0f);

    // ---- phase 1: accumulate aggm@W1l then x@W1r ----
#pragma unroll
    for (int s = 0; s < 2; s++) {
        const float* Wsrc = s ? W1r : W1l;
        for (int ck = 0; ck < 4; ck++) {
            __syncthreads();
            // stage weights [32 x 128]: 1024 float4, row = i>>5 (0..31), c4 = i&31
            for (int i = tid; i < 1024; i += 256) {
                int row = i >> 5, c4 = i & 31;
                *reinterpret_cast<float4*>(Ws + row * WSTR + c4 * 4) =
                    reinterpret_cast<const float4*>(Wsrc)[(ck * 32 + row) * 32 + c4];
            }
            // stage A tile [64 x 32]: 512 float4
            for (int i = tid; i < 512; i += 256) {
                int r = i >> 3, c4 = i & 7;
                int node = base + r;
                float4 v = make_float4(0.f, 0.f, 0.f, 0.f);
                if (node < nNodes) {
                    const float* Asrc = s ? (x + (size_t)node * 128)
                                          : (g_aggm + (size_t)node * 128);
                    v = reinterpret_cast<const float4*>(Asrc)[ck * 8 + c4];
                }
                *reinterpret_cast<float4*>(As + r * ASTR + c4 * 4) = v;
            }
            __syncthreads();

#pragma unroll
            for (int k0 = 0; k0 < 32; k0 += 8) {
                FragA af;
                wmma::load_matrix_sync(af, As + wr * 16 * ASTR + k0, ASTR);
                cvt_tf32(af);
#pragma unroll
                for (int j = 0; j < 4; j++) {
                    FragB bf;
                    wmma::load_matrix_sync(bf, Ws + k0 * WSTR + wc * 64 + j * 16, WSTR);
                    cvt_tf32(bf);
                    wmma::mma_sync(acc[j], af, bf, acc[j]);
                }
            }
        }
    }

    // ---- phase 1 epilogue: acc -> Hs, bias+relu, write g_h ----
    __syncthreads();
#pragma unroll
    for (int j = 0; j < 4; j++)
        wmma::store_matrix_sync(Hs + wr * 16 * HSTR + wc * 64 + j * 16, acc[j],
                                HSTR, wmma::mem_row_major);
    __syncthreads();
    for (int i = tid; i < 2048; i += 256) {
        int r = i >> 5, c4 = i & 31;
        float4 v = *reinterpret_cast<float4*>(Hs + r * HSTR + c4 * 4);
        float4 bb = reinterpret_cast<const float4*>(b1)[c4];
        v.x = fmaxf(v.x + bb.x, 0.f);
        v.y = fmaxf(v.y + bb.y, 0.f);
        v.z = fmaxf(v.z + bb.z, 0.f);
        v.w = fmaxf(v.w + bb.w, 0.f);
        *reinterpret_cast<float4*>(Hs + r * HSTR + c4 * 4) = v;
        *reinterpret_cast<float4*>(g_h + (size_t)(base + r) * 128 + c4 * 4) = v;  // padded
    }

    // ---- phase 2: t2 = Hs @ W2l ----
    const int r2 = wid >> 1;
    const int cb = (wid & 1) * 2;
    FragC a2[2];
    wmma::fill_fragment(a2[0], 0.0f);
    wmma::fill_fragment(a2[1], 0.0f);

    for (int ck = 0; ck < 4; ck++) {
        __syncthreads();
        for (int i = tid; i < 512; i += 256) {
            int row = i >> 4, c4 = i & 15;
            *reinterpret_cast<float4*>(W2s + row * W2STR + c4 * 4) =
                reinterpret_cast<const float4*>(W2l)[(ck * 32 + row) * 16 + c4];
        }
        __syncthreads();
#pragma unroll
        for (int k0 = 0; k0 < 32; k0 += 8) {
            FragA af;
            wmma::load_matrix_sync(af, Hs + r2 * 16 * HSTR + ck * 32 + k0, HSTR);
            cvt_tf32(af);
#pragma unroll
            for (int j = 0; j < 2; j++) {
                FragB bf;
                wmma::load_matrix_sync(bf, W2s + k0 * W2STR + (cb + j) * 16, W2STR);
                cvt_tf32(bf);
                wmma::mma_sync(a2[j], af, bf, a2[j]);
            }
        }
    }
#pragma unroll
    for (int j = 0; j < 2; j++)
        wmma::store_matrix_sync(g_t2 + (size_t)(base + r2 * 16) * 64 + (cb + j) * 16,
                                a2[j], 64, wmma::mem_row_major);   // padded buffer
}

// ---------------- final GEMM: out = h @ W2r + b2 + aggm2 (WMMA tf32) ----------
__global__ void __launch_bounds__(256)
gemm3_kernel(const float* __restrict__ W2r, const float* __restrict__ b2,
             float* __restrict__ outp, int nNodes) {
    constexpr int WSTR = 68;    // Ws3 row stride (64 cols)
    constexpr int ASTR = 36;    // As3 row stride (32 cols)
    constexpr int OSTR = 68;    // Os  row stride (64 cols)

    __shared__ __align__(16) float smem[4480];    // 17920 B
    float* Ws3 = smem;                 // [32 x 68]  (0..2176)
    float* As3 = smem + 2176;          // [64 x 36]  (2176..4480)
    float* Os  = smem;                 // [64 x 68]  epilogue (0..4352)

    const int tid = threadIdx.x;
    const int wid = tid >> 5;
    const int r   = wid >> 1;
    const int cb  = (wid & 1) * 2;

    const int base = blockIdx.x * 64;

    FragC acc[2];
    wmma::fill_fragment(acc[0], 0.0f);
    wmma::fill_fragment(acc[1], 0.0f);

    for (int ck = 0; ck < 4; ck++) {
        __syncthreads();
        for (int i = tid; i < 512; i += 256) {
            int row = i >> 4, c4 = i & 15;
            *reinterpret_cast<float4*>(Ws3 + row * WSTR + c4 * 4) =
                reinterpret_cast<const float4*>(W2r)[(ck * 32 + row) * 16 + c4];
        }
        for (int i = tid; i < 512; i += 256) {
            int rr = i >> 3, c4 = i & 7;
            int node = base + rr;
            float4 v = make_float4(0.f, 0.f, 0.f, 0.f);
            if (node < nNodes)
                v = reinterpret_cast<const float4*>(g_h + (size_t)node * 128)[ck * 8 + c4];
            *reinterpret_cast<float4*>(As3 + rr * ASTR + c4 * 4) = v;
        }
        __syncthreads();
#pragma unroll
        for (int k0 = 0; k0 < 32; k0 += 8) {
            FragA af;
            wmma::load_matrix_sync(af, As3 + r * 16 * ASTR + k0, ASTR);
            cvt_tf32(af);
#pragma unroll
            for (int j = 0; j < 2; j++) {
                FragB bf;
                wmma::load_matrix_sync(bf, Ws3 + k0 * WSTR + (cb + j) * 16, WSTR);
                cvt_tf32(bf);
                wmma::mma_sync(acc[j], af, bf, acc[j]);
            }
        }
    }

    __syncthreads();
#pragma unroll
    for (int j = 0; j < 2; j++)
        wmma::store_matrix_sync(Os + r * 16 * OSTR + (cb + j) * 16, acc[j],
                                OSTR, wmma::mem_row_major);
    __syncthreads();

    for (int i = tid; i < 1024; i += 256) {
        int rr = i >> 4, c4 = i & 15;
        int node = base + rr;
        if (node >= nNodes) continue;
        float4 v = *reinterpret_cast<float4*>(Os + rr * OSTR + c4 * 4);
        float4 bb = reinterpret_cast<const float4*>(b2)[c4];
        float4 sv = reinterpret_cast<const float4*>(g_aggm2 + (size_t)node * 64)[c4];
        v.x += bb.x + sv.x;
        v.y += bb.y + sv.y;
        v.z += bb.z + sv.z;
        v.w += bb.w + sv.w;
        *reinterpret_cast<float4*>(outp + (size_t)node * 64 + c4 * 4) = v;
    }
}

// ---------------- launch -------------------------------------------------------
extern "C" void kernel_launch(void* const* d_in, const int* in_sizes, int n_in,
                              void* d_out, int out_size) {
    const float* x       = (const float*)d_in[0];
    const int*   ei_w    = (const int*)d_in[1];
    const float* W1l     = (const float*)d_in[2];
    const float* b1      = (const float*)d_in[3];
    const float* W1r     = (const float*)d_in[4];
    const float* W2l     = (const float*)d_in[5];
    const float* b2      = (const float*)d_in[6];
    const float* W2r     = (const float*)d_in[7];
    float* out = (float*)d_out;

    int N = in_sizes[0] / 128;
    int E = in_sizes[1] / 2;
    int nblk = (N + SCAN_BLK - 1) / SCAN_BLK;

    // --- decode + CSR build (int atomics only) ---
    detect_kernel<<<1, 256>>>(ei_w);
    zero_cnt_kernel<<<(N + 256) / 256, 256>>>(N);
    convert_hist_kernel<<<(E + 255) / 256, 256>>>(ei_w, E, N);
    scan_blk_kernel<<<nblk, SCAN_BLK>>>(N);
    scan_top_kernel<<<1, SCAN_BLK>>>(nblk, N);
    scan_add_kernel<<<nblk, SCAN_BLK>>>(N);
    fill_kernel<<<(E + 255) / 256, 256>>>(E);

    // --- layer 1 (+ layer-2 transform fused) ---
    {
        size_t threads = (size_t)N * 32;
        agg_mean128_kernel<<<(int)((threads + 255) / 256), 256>>>(x, N);
    }
    gemm1_fused<<<(N + 63) / 64, 256>>>(x, W1l, W1r, b1, W2l, N);

    // --- layer 2: mean-gather of t2, final GEMM ---
    {
        size_t threads = (size_t)N * 32;
        agg_mean64_kernel<<<(int)((threads + 255) / 256), 256>>>(N);
    }
    gemm3_kernel<<<(N + 63) / 64, 256>>>(W2r, b2, out, N);
}

// round 10
// speedup vs baseline: 1.6189x; 1.0436x over previous
#include <cuda_runtime.h>
#include <mma.h>
#include <cstdint>

using namespace nvcuda;

#define MAXN 50176
#define MAXE 800000
#define SCAN_BLK 256

// ---------------- scratch (device globals; no allocation allowed) -----------
__device__ int   g_is64;                           // edge dtype flag
__device__ int   g_src[MAXE];                      // decoded src ids (int32)
__device__ int   g_dst[MAXE];                      // decoded dst ids (int32)
__device__ int   g_cnt[MAXN + 1];                  // histogram
__device__ int   g_rowptr[MAXN + 1];               // CSR row pointers
__device__ int   g_cur[MAXN + 1];                  // fill cursors
__device__ int   g_csr[MAXE];                      // src ids grouped by dst
__device__ int   g_blksum[256];                    // scan phase-1 block sums
__device__ float g_h[(size_t)MAXN * 128];          // layer-1 output (padded)
__device__ float g_t2[(size_t)MAXN * 64];          // h @ W2l (padded)

// ---------------- detect dtype + zero counters (fused) ------------------------
__global__ void detect_zero_kernel(const int* __restrict__ w, int N, int nblk) {
    if ((int)blockIdx.x == nblk) {
        // last block: dtype detect. int64 values < 2^31 => odd words all zero.
        __shared__ int nonzero;
        if (threadIdx.x == 0) nonzero = 0;
        __syncthreads();
        int nz = 0;
        for (int i = threadIdx.x; i < 1024; i += 256)
            if (w[2 * i + 1] != 0) nz = 1;
        if (nz) nonzero = 1;          // benign race
        __syncthreads();
        if (threadIdx.x == 0) g_is64 = (nonzero == 0) ? 1 : 0;
        return;
    }
    int i = blockIdx.x * blockDim.x + threadIdx.x;
    if (i <= N) g_cnt[i] = 0;
}

// ---------------- decode + histogram ------------------------------------------
__global__ void convert_hist_kernel(const int* __restrict__ w, int E, int N) {
    int e = blockIdx.x * blockDim.x + threadIdx.x;
    if (e >= E) return;
    int s, d;
    if (g_is64) {
        s = w[2 * e];
        d = w[2 * (E + e)];
    } else {
        s = w[e];
        d = w[E + e];
    }
    s = min(max(s, 0), N - 1);        // clamp: never trap on bad data
    d = min(max(d, 0), N - 1);
    g_src[e] = s;
    g_dst[e] = d;
    atomicAdd(&g_cnt[d], 1);
}

// ---------------- two-kernel exclusive scan ------------------------------------
__device__ __forceinline__ int block_incl_scan(int v, int* wsum) {
    int lane = threadIdx.x & 31;
    int w = threadIdx.x >> 5;
    int x = v;
#pragma unroll
    for (int o = 1; o < 32; o <<= 1) {
        int y = __shfl_up_sync(0xffffffffu, x, o);
        if (lane >= o) x += y;
    }
    if (lane == 31) wsum[w] = x;
    __syncthreads();
    if (w == 0 && lane < 8) {
        int s = wsum[lane];
#pragma unroll
        for (int o = 1; o < 8; o <<= 1) {
            int y = __shfl_up_sync(0xffu, s, o);
            if (lane >= o) s += y;
        }
        wsum[lane] = s;
    }
    __syncthreads();
    return x + (w > 0 ? wsum[w - 1] : 0);
}

__global__ void __launch_bounds__(SCAN_BLK) scan_blk_kernel(int N) {
    __shared__ int wsum[8];
    int i = blockIdx.x * SCAN_BLK + threadIdx.x;
    int v = (i < N) ? g_cnt[i] : 0;
    int incl = block_incl_scan(v, wsum);
    if (i < N) g_rowptr[i] = incl - v;
    if (threadIdx.x == SCAN_BLK - 1) g_blksum[blockIdx.x] = incl;
}

// each block redundantly computes its own global offset from the 196 block sums
__global__ void __launch_bounds__(SCAN_BLK) scan_finish_kernel(int nblk, int N) {
    __shared__ int ssum[SCAN_BLK];
    int bid = blockIdx.x;
    int tid = threadIdx.x;
    int partial = 0;
    for (int j = tid; j < bid; j += SCAN_BLK) partial += g_blksum[j];
    ssum[tid] = partial;
    __syncthreads();
    for (int s = SCAN_BLK / 2; s > 0; s >>= 1) {
        if (tid < s) ssum[tid] += ssum[tid + s];
        __syncthreads();
    }
    int off = ssum[0];
    int i = bid * SCAN_BLK + tid;
    if (i < N) {
        int r = g_rowptr[i] + off;
        g_rowptr[i] = r;
        g_cur[i] = r;
    }
    if (bid == nblk - 1 && tid == 0)
        g_rowptr[N] = off + g_blksum[bid];
}

__global__ void fill_kernel(int E) {
    int e = blockIdx.x * blockDim.x + threadIdx.x;
    if (e >= E) return;
    int pos = atomicAdd(&g_cur[g_dst[e]], 1);
    g_csr[pos] = g_src[e];
}

// ---------------- WMMA helpers -------------------------------------------------
using FragA = wmma::fragment<wmma::matrix_a, 16, 16, 8, wmma::precision::tf32, wmma::row_major>;
using FragB = wmma::fragment<wmma::matrix_b, 16, 16, 8, wmma::precision::tf32, wmma::row_major>;
using FragC = wmma::fragment<wmma::accumulator, 16, 16, 8, float>;

__device__ __forceinline__ void cvt_tf32(FragA& f) {
#pragma unroll
    for (int i = 0; i < f.num_elements; i++) f.x[i] = wmma::__float_to_tf32(f.x[i]);
}
__device__ __forceinline__ void cvt_tf32(FragB& f) {
#pragma unroll
    for (int i = 0; i < f.num_elements; i++) f.x[i] = wmma::__float_to_tf32(f.x[i]);
}

// ---------------- mega kernel 1: gather + layer-1 GEMM + layer-2 transform ----
// Phase 0: As[n,:] = mean of x over in-neighbors (warp-per-node gather)
// Phase 1: h = relu(As @ W1l + x @ W1r + b1) -> Hs, g_h
// Phase 2: t2 = Hs @ W2l -> g_t2
__global__ void __launch_bounds__(256)
gemm1_mega(const float* __restrict__ x, const float* __restrict__ W1l,
           const float* __restrict__ W1r, const float* __restrict__ b1,
           const float* __restrict__ W2l, int N) {
    constexpr int ASTR = 132;   // As/Hs row stride (128 cols)
    constexpr int WSTR = 132;   // Ws row stride (128 cols)
    constexpr int W2STR = 68;   // W2s row stride (64 cols)

    __shared__ __align__(16) float As[64 * ASTR];   // 33792 B, aliases Hs
    __shared__ __align__(16) float Ws[16 * WSTR];   // 8448 B, aliases W2s
    float* Hs  = As;
    float* W2s = Ws;

    const int tid  = threadIdx.x;
    const int wid  = tid >> 5;
    const int lane = tid & 31;
    const int base = blockIdx.x * 64;

    // ---- phase 0: gather-mean of x into As (full 128 ch per node) ----
    for (int n = wid; n < 64; n += 8) {
        int node = base + n;
        float4 a0 = make_float4(0.f, 0.f, 0.f, 0.f);
        float4 a1 = make_float4(0.f, 0.f, 0.f, 0.f);
        float rd = 0.f;
        if (node < N) {
            int beg = g_rowptr[node];
            int end = g_rowptr[node + 1];
            int i = beg;
            for (; i + 1 < end; i += 2) {
                int s0 = g_csr[i];
                int s1 = g_csr[i + 1];
                float4 v0 = reinterpret_cast<const float4*>(x + (size_t)s0 * 128)[lane];
                float4 v1 = reinterpret_cast<const float4*>(x + (size_t)s1 * 128)[lane];
                a0.x += v0.x; a0.y += v0.y; a0.z += v0.z; a0.w += v0.w;
                a1.x += v1.x; a1.y += v1.y; a1.z += v1.z; a1.w += v1.w;
            }
            if (i < end) {
                int s0 = g_csr[i];
                float4 v0 = reinterpret_cast<const float4*>(x + (size_t)s0 * 128)[lane];
                a0.x += v0.x; a0.y += v0.y; a0.z += v0.z; a0.w += v0.w;
            }
            int deg = end - beg;
            rd = (deg > 0) ? (1.0f / (float)deg) : 0.0f;
        }
        float4 r;
        r.x = (a0.x + a1.x) * rd;
        r.y = (a0.y + a1.y) * rd;
        r.z = (a0.z + a1.z) * rd;
        r.w = (a0.w + a1.w) * rd;
        *reinterpret_cast<float4*>(As + n * ASTR + lane * 4) = r;
    }
    __syncthreads();

    // ---- phase 1 GEMM: two A-sources x two weight matrices ----
    const int wr = wid >> 1;           // 4 row chunks of 16 nodes
    const int wc = wid & 1;            // 2 col halves of 64

    FragC acc[4];
#pragma unroll
    for (int j = 0; j < 4; j++) wmma::fill_fragment(acc[j], 0.0f);

#pragma unroll
    for (int s = 0; s < 2; s++) {
        const float* Wsrc = s ? W1r : W1l;
        if (s == 1) {
            __syncthreads();           // all warps done with mean-As reads
            for (int i = tid; i < 2048; i += 256) {
                int r = i >> 5, c4 = i & 31;
                int node = base + r;
                float4 v = make_float4(0.f, 0.f, 0.f, 0.f);
                if (node < N)
                    v = reinterpret_cast<const float4*>(x + (size_t)node * 128)[c4];
                *reinterpret_cast<float4*>(As + r * ASTR + c4 * 4) = v;
            }
            __syncthreads();
        }
        for (int ck = 0; ck < 8; ck++) {
            __syncthreads();
            // stage weight chunk [16 x 128]: 512 float4
            for (int i = tid; i < 512; i += 256) {
                int row = i >> 5, c4 = i & 31;
                *reinterpret_cast<float4*>(Ws + row * WSTR + c4 * 4) =
                    reinterpret_cast<const float4*>(Wsrc)[(ck * 16 + row) * 32 + c4];
            }
            __syncthreads();
#pragma unroll
            for (int k0 = 0; k0 < 16; k0 += 8) {
                FragA af;
                wmma::load_matrix_sync(af, As + wr * 16 * ASTR + ck * 16 + k0, ASTR);
                cvt_tf32(af);
#pragma unroll
                for (int j = 0; j < 4; j++) {
                    FragB bf;
                    wmma::load_matrix_sync(bf, Ws + k0 * WSTR + wc * 64 + j * 16, WSTR);
                    cvt_tf32(bf);
                    wmma::mma_sync(acc[j], af, bf, acc[j]);
                }
            }
        }
    }

    // ---- phase 1 epilogue: acc -> Hs (aliases As), bias+relu, write g_h ----
    __syncthreads();
#pragma unroll
    for (int j = 0; j < 4; j++)
        wmma::store_matrix_sync(Hs + wr * 16 * ASTR + wc * 64 + j * 16, acc[j],
                                ASTR, wmma::mem_row_major);
    __syncthreads();
    for (int i = tid; i < 2048; i += 256) {
        int r = i >> 5, c4 = i & 31;
        float4 v = *reinterpret_cast<float4*>(Hs + r * ASTR + c4 * 4);
        float4 bb = reinterpret_cast<const float4*>(b1)[c4];
        v.x = fmaxf(v.x + bb.x, 0.f);
        v.y = fmaxf(v.y + bb.y, 0.f);
        v.z = fmaxf(v.z + bb.z, 0.f);
        v.w = fmaxf(v.w + bb.w, 0.f);
        *reinterpret_cast<float4*>(Hs + r * ASTR + c4 * 4) = v;
        *reinterpret_cast<float4*>(g_h + (size_t)(base + r) * 128 + c4 * 4) = v;
    }

    // ---- phase 2: t2 = Hs @ W2l ----
    const int r2 = wid >> 1;
    const int cb = (wid & 1) * 2;
    FragC a2[2];
    wmma::fill_fragment(a2[0], 0.0f);
    wmma::fill_fragment(a2[1], 0.0f);

    for (int ck = 0; ck < 8; ck++) {
        __syncthreads();
        {   // stage W2l chunk [16 x 64]: 256 float4, 1 per thread
            int row = tid >> 4, c4 = tid & 15;
            *reinterpret_cast<float4*>(W2s + row * W2STR + c4 * 4) =
                reinterpret_cast<const float4*>(W2l)[(ck * 16 + row) * 16 + c4];
        }
        __syncthreads();
#pragma unroll
        for (int k0 = 0; k0 < 16; k0 += 8) {
            FragA af;
            wmma::load_matrix_sync(af, Hs + r2 * 16 * ASTR + ck * 16 + k0, ASTR);
            cvt_tf32(af);
#pragma unroll
            for (int j = 0; j < 2; j++) {
                FragB bf;
                wmma::load_matrix_sync(bf, W2s + k0 * W2STR + (cb + j) * 16, W2STR);
                cvt_tf32(bf);
                wmma::mma_sync(a2[j], af, bf, a2[j]);
            }
        }
    }
#pragma unroll
    for (int j = 0; j < 2; j++)
        wmma::store_matrix_sync(g_t2 + (size_t)(base + r2 * 16) * 64 + (cb + j) * 16,
                                a2[j], 64, wmma::mem_row_major);   // padded buffer
}

// ---------------- mega kernel 2: gather t2 + final GEMM ------------------------
// Phase 0: Ss[n,:] = mean of t2 over in-neighbors
// Phase 1: out = h @ W2r + b2 + Ss
__global__ void __launch_bounds__(256)
gemm3_mega(const float* __restrict__ W2r, const float* __restrict__ b2,
           float* __restrict__ outp, int N) {
    constexpr int SSTR = 68;    // Ss row stride (64 cols)
    constexpr int ASTR = 36;    // As3 row stride (32 cols)
    constexpr int WSTR = 68;    // Ws3 row stride (64 cols)
    constexpr int OSTR = 68;    // Os row stride (64 cols)

    __shared__ __align__(16) float Ss[64 * SSTR];   // 17408 B
    __shared__ __align__(16) float Bf[4480];        // 17920 B
    float* As3 = Bf;                   // [64 x 36] = 2304 floats
    float* Ws3 = Bf + 2304;            // [32 x 68] = 2176 floats
    float* Os  = Bf;                   // epilogue: [64 x 68] = 4352 floats

    const int tid  = threadIdx.x;
    const int wid  = tid >> 5;
    const int lane = tid & 31;
    const int base = blockIdx.x * 64;

    // ---- phase 0: gather-mean of t2 into Ss ----
    for (int n = wid; n < 64; n += 8) {
        int node = base + n;
        float2 a0 = make_float2(0.f, 0.f);
        float2 a1 = make_float2(0.f, 0.f);
        float rd = 0.f;
        if (node < N) {
            int beg = g_rowptr[node];
            int end = g_rowptr[node + 1];
            int i = beg;
            for (; i + 1 < end; i += 2) {
                int s0 = g_csr[i];
                int s1 = g_csr[i + 1];
                float2 v0 = reinterpret_cast<const float2*>(g_t2 + (size_t)s0 * 64)[lane];
                float2 v1 = reinterpret_cast<const float2*>(g_t2 + (size_t)s1 * 64)[lane];
                a0.x += v0.x; a0.y += v0.y;
                a1.x += v1.x; a1.y += v1.y;
            }
            if (i < end) {
                int s0 = g_csr[i];
                float2 v0 = reinterpret_cast<const float2*>(g_t2 + (size_t)s0 * 64)[lane];
                a0.x += v0.x; a0.y += v0.y;
            }
            int deg = end - beg;
            rd = (deg > 0) ? (1.0f / (float)deg) : 0.0f;
        }
        float2 r;
        r.x = (a0.x + a1.x) * rd;
        r.y = (a0.y + a1.y) * rd;
        *reinterpret_cast<float2*>(Ss + n * SSTR + lane * 2) = r;
    }
    __syncthreads();

    // ---- phase 1 GEMM: h @ W2r ----
    const int r  = wid >> 1;
    const int cb = (wid & 1) * 2;

    FragC acc[2];
    wmma::fill_fragment(acc[0], 0.0f);
    wmma::fill_fragment(acc[1], 0.0f);

    for (int ck = 0; ck < 4; ck++) {
        __syncthreads();
        for (int i = tid; i < 512; i += 256) {
            int row = i >> 4, c4 = i & 15;
            *reinterpret_cast<float4*>(Ws3 + row * WSTR + c4 * 4) =
                reinterpret_cast<const float4*>(W2r)[(ck * 32 + row) * 16 + c4];
        }
        for (int i = tid; i < 512; i += 256) {
            int rr = i >> 3, c4 = i & 7;
            int node = base + rr;
            float4 v = make_float4(0.f, 0.f, 0.f, 0.f);
            if (node < N)
                v = reinterpret_cast<const float4*>(g_h + (size_t)node * 128)[ck * 8 + c4];
            *reinterpret_cast<float4*>(As3 + rr * ASTR + c4 * 4) = v;
        }
        __syncthreads();
#pragma unroll
        for (int k0 = 0; k0 < 32; k0 += 8) {
            FragA af;
            wmma::load_matrix_sync(af, As3 + r * 16 * ASTR + k0, ASTR);
            cvt_tf32(af);
#pragma unroll
            for (int j = 0; j < 2; j++) {
                FragB bf;
                wmma::load_matrix_sync(bf, Ws3 + k0 * WSTR + (cb + j) * 16, WSTR);
                cvt_tf32(bf);
                wmma::mma_sync(acc[j], af, bf, acc[j]);
            }
        }
    }

    __syncthreads();
#pragma unroll
    for (int j = 0; j < 2; j++)
        wmma::store_matrix_sync(Os + r * 16 * OSTR + (cb + j) * 16, acc[j],
                                OSTR, wmma::mem_row_major);
    __syncthreads();

    for (int i = tid; i < 1024; i += 256) {
        int rr = i >> 4, c4 = i & 15;
        int node = base + rr;
        if (node >= N) continue;
        float4 v = *reinterpret_cast<float4*>(Os + rr * OSTR + c4 * 4);
        float4 bb = reinterpret_cast<const float4*>(b2)[c4];
        float4 sv = *reinterpret_cast<const float4*>(Ss + rr * SSTR + c4 * 4);
        v.x += bb.x + sv.x;
        v.y += bb.y + sv.y;
        v.z += bb.z + sv.z;
        v.w += bb.w + sv.w;
        *reinterpret_cast<float4*>(outp + (size_t)node * 64 + c4 * 4) = v;
    }
}

// ---------------- launch -------------------------------------------------------
extern "C" void kernel_launch(void* const* d_in, const int* in_sizes, int n_in,
                              void* d_out, int out_size) {
    const float* x       = (const float*)d_in[0];
    const int*   ei_w    = (const int*)d_in[1];
    const float* W1l     = (const float*)d_in[2];
    const float* b1      = (const float*)d_in[3];
    const float* W1r     = (const float*)d_in[4];
    const float* W2l     = (const float*)d_in[5];
    const float* b2      = (const float*)d_in[6];
    const float* W2r     = (const float*)d_in[7];
    float* out = (float*)d_out;

    int N = in_sizes[0] / 128;
    int E = in_sizes[1] / 2;
    int nblk = (N + SCAN_BLK - 1) / SCAN_BLK;

    // --- decode + CSR build (4 launches) ---
    detect_zero_kernel<<<nblk + 1, 256>>>(ei_w, N, nblk);
    convert_hist_kernel<<<(E + 255) / 256, 256>>>(ei_w, E, N);
    scan_blk_kernel<<<nblk, SCAN_BLK>>>(N);
    scan_finish_kernel<<<nblk, SCAN_BLK>>>(nblk, N);
    fill_kernel<<<(E + 255) / 256, 256>>>(E);

    // --- layer 1 (gather + dual GEMM + layer-2 transform) ---
    gemm1_mega<<<(N + 63) / 64, 256>>>(x, W1l, W1r, b1, W2l, N);

    // --- layer 2 (gather t2 + final GEMM) ---
    gemm3_mega<<<(N + 63) / 64, 256>>>(W2r, b2, out, N);
}

// round 11
// speedup vs baseline: 1.7406x; 1.0752x over previous
#include <cuda_runtime.h>
#include <mma.h>
#include <cstdint>

using namespace nvcuda;

#define MAXN 50176
#define MAXE 800000
#define SCAN_BLK 256

// ---------------- scratch (device globals; no allocation allowed) -----------
__device__ int   g_is64;                           // edge dtype flag
__device__ int   g_src[MAXE];                      // decoded src ids (int32)
__device__ int   g_dst[MAXE];                      // decoded dst ids (int32)
__device__ int   g_cnt[MAXN + 1];                  // histogram
__device__ int   g_rowptr[MAXN + 1];               // CSR row pointers
__device__ int   g_cur[MAXN + 1];                  // fill cursors
__device__ int   g_csr[MAXE];                      // src ids grouped by dst
__device__ int   g_blksum[256];                    // scan phase-1 block sums
__device__ float g_t2[(size_t)MAXN * 64];          // h @ W2l (padded)
__device__ float g_opart[(size_t)MAXN * 64];       // h @ W2r (padded)

// ---------------- detect dtype + zero counters (fused) ------------------------
__global__ void detect_zero_kernel(const int* __restrict__ w, int N, int nblk) {
    if ((int)blockIdx.x == nblk) {
        __shared__ int nonzero;
        if (threadIdx.x == 0) nonzero = 0;
        __syncthreads();
        int nz = 0;
        for (int i = threadIdx.x; i < 1024; i += 256)
            if (w[2 * i + 1] != 0) nz = 1;
        if (nz) nonzero = 1;          // benign race
        __syncthreads();
        if (threadIdx.x == 0) g_is64 = (nonzero == 0) ? 1 : 0;
        return;
    }
    int i = blockIdx.x * blockDim.x + threadIdx.x;
    if (i <= N) g_cnt[i] = 0;
}

// ---------------- decode + histogram ------------------------------------------
__global__ void convert_hist_kernel(const int* __restrict__ w, int E, int N) {
    int e = blockIdx.x * blockDim.x + threadIdx.x;
    if (e >= E) return;
    int s, d;
    if (g_is64) {
        s = w[2 * e];
        d = w[2 * (E + e)];
    } else {
        s = w[e];
        d = w[E + e];
    }
    s = min(max(s, 0), N - 1);        // clamp: never trap on bad data
    d = min(max(d, 0), N - 1);
    g_src[e] = s;
    g_dst[e] = d;
    atomicAdd(&g_cnt[d], 1);
}

// ---------------- two-kernel exclusive scan ------------------------------------
__device__ __forceinline__ int block_incl_scan(int v, int* wsum) {
    int lane = threadIdx.x & 31;
    int w = threadIdx.x >> 5;
    int x = v;
#pragma unroll
    for (int o = 1; o < 32; o <<= 1) {
        int y = __shfl_up_sync(0xffffffffu, x, o);
        if (lane >= o) x += y;
    }
    if (lane == 31) wsum[w] = x;
    __syncthreads();
    if (w == 0 && lane < 8) {
        int s = wsum[lane];
#pragma unroll
        for (int o = 1; o < 8; o <<= 1) {
            int y = __shfl_up_sync(0xffu, s, o);
            if (lane >= o) s += y;
        }
        wsum[lane] = s;
    }
    __syncthreads();
    return x + (w > 0 ? wsum[w - 1] : 0);
}

__global__ void __launch_bounds__(SCAN_BLK) scan_blk_kernel(int N) {
    __shared__ int wsum[8];
    int i = blockIdx.x * SCAN_BLK + threadIdx.x;
    int v = (i < N) ? g_cnt[i] : 0;
    int incl = block_incl_scan(v, wsum);
    if (i < N) g_rowptr[i] = incl - v;
    if (threadIdx.x == SCAN_BLK - 1) g_blksum[blockIdx.x] = incl;
}

__global__ void __launch_bounds__(SCAN_BLK) scan_finish_kernel(int nblk, int N) {
    __shared__ int ssum[SCAN_BLK];
    int bid = blockIdx.x;
    int tid = threadIdx.x;
    int partial = 0;
    for (int j = tid; j < bid; j += SCAN_BLK) partial += g_blksum[j];
    ssum[tid] = partial;
    __syncthreads();
    for (int s = SCAN_BLK / 2; s > 0; s >>= 1) {
        if (tid < s) ssum[tid] += ssum[tid + s];
        __syncthreads();
    }
    int off = ssum[0];
    int i = bid * SCAN_BLK + tid;
    if (i < N) {
        int r = g_rowptr[i] + off;
        g_rowptr[i] = r;
        g_cur[i] = r;
    }
    if (bid == nblk - 1 && tid == 0)
        g_rowptr[N] = off + g_blksum[bid];
}

__global__ void fill_kernel(int E) {
    int e = blockIdx.x * blockDim.x + threadIdx.x;
    if (e >= E) return;
    int pos = atomicAdd(&g_cur[g_dst[e]], 1);
    g_csr[pos] = g_src[e];
}

// ---------------- WMMA helpers -------------------------------------------------
using FragA = wmma::fragment<wmma::matrix_a, 16, 16, 8, wmma::precision::tf32, wmma::row_major>;
using FragB = wmma::fragment<wmma::matrix_b, 16, 16, 8, wmma::precision::tf32, wmma::row_major>;
using FragC = wmma::fragment<wmma::accumulator, 16, 16, 8, float>;

__device__ __forceinline__ void cvt_tf32(FragA& f) {
#pragma unroll
    for (int i = 0; i < f.num_elements; i++) f.x[i] = wmma::__float_to_tf32(f.x[i]);
}
__device__ __forceinline__ void cvt_tf32(FragB& f) {
#pragma unroll
    for (int i = 0; i < f.num_elements; i++) f.x[i] = wmma::__float_to_tf32(f.x[i]);
}

// ---------------- mega kernel: gather + layer-1 GEMM + both layer-2 transforms -
// Phase 0: As[n,:] = mean of x over in-neighbors (warp-per-node gather)
// Phase 1: h = relu(As @ W1l + x @ W1r + b1) -> Hs (smem only)
// Phase 2: t2 = Hs @ W2l -> g_t2 ; o_part = Hs @ W2r -> g_opart
__global__ void __launch_bounds__(256)
gemm1_mega(const float* __restrict__ x, const float* __restrict__ W1l,
           const float* __restrict__ W1r, const float* __restrict__ b1,
           const float* __restrict__ W2l, const float* __restrict__ W2r, int N) {
    constexpr int ASTR = 132;    // As/Hs row stride (128 cols)
    constexpr int WSTR = 132;    // Ws row stride (128 cols)
    constexpr int W2STR = 68;    // W2s/W3s row stride (64 cols)

    // [As/Hs: 8448 floats][W region: 2176 floats] = 10624 floats = 42496 B
    __shared__ __align__(16) float smem[10624];
    float* As  = smem;                       // phase 0/1 A tile, phase 1 epi = Hs
    float* Hs  = smem;
    float* Ws  = smem + 64 * ASTR;           // phase 1 weights [16 x 132]
    float* W2s = smem + 64 * ASTR;           // phase 2: [16 x 68]
    float* W3s = W2s + 16 * W2STR;           // phase 2: [16 x 68]

    const int tid  = threadIdx.x;
    const int wid  = tid >> 5;
    const int lane = tid & 31;
    const int base = blockIdx.x * 64;

    // ---- phase 0: gather-mean of x into As ----
    for (int n = wid; n < 64; n += 8) {
        int node = base + n;
        float4 a0 = make_float4(0.f, 0.f, 0.f, 0.f);
        float4 a1 = make_float4(0.f, 0.f, 0.f, 0.f);
        float rd = 0.f;
        if (node < N) {
            int beg = g_rowptr[node];
            int end = g_rowptr[node + 1];
            int i = beg;
            for (; i + 1 < end; i += 2) {
                int s0 = g_csr[i];
                int s1 = g_csr[i + 1];
                float4 v0 = reinterpret_cast<const float4*>(x + (size_t)s0 * 128)[lane];
                float4 v1 = reinterpret_cast<const float4*>(x + (size_t)s1 * 128)[lane];
                a0.x += v0.x; a0.y += v0.y; a0.z += v0.z; a0.w += v0.w;
                a1.x += v1.x; a1.y += v1.y; a1.z += v1.z; a1.w += v1.w;
            }
            if (i < end) {
                int s0 = g_csr[i];
                float4 v0 = reinterpret_cast<const float4*>(x + (size_t)s0 * 128)[lane];
                a0.x += v0.x; a0.y += v0.y; a0.z += v0.z; a0.w += v0.w;
            }
            int deg = end - beg;
            rd = (deg > 0) ? (1.0f / (float)deg) : 0.0f;
        }
        float4 r;
        r.x = (a0.x + a1.x) * rd;
        r.y = (a0.y + a1.y) * rd;
        r.z = (a0.z + a1.z) * rd;
        r.w = (a0.w + a1.w) * rd;
        *reinterpret_cast<float4*>(As + n * ASTR + lane * 4) = r;
    }
    __syncthreads();

    // ---- phase 1 GEMM: mean@W1l then x@W1r ----
    const int wr = wid >> 1;           // 4 row chunks of 16 nodes
    const int wc = wid & 1;            // 2 col halves of 64

    FragC acc[4];
#pragma unroll
    for (int j = 0; j < 4; j++) wmma::fill_fragment(acc[j], 0.0f);

#pragma unroll
    for (int s = 0; s < 2; s++) {
        const float* Wsrc = s ? W1r : W1l;
        if (s == 1) {
            __syncthreads();
            for (int i = tid; i < 2048; i += 256) {
                int r = i >> 5, c4 = i & 31;
                int node = base + r;
                float4 v = make_float4(0.f, 0.f, 0.f, 0.f);
                if (node < N)
                    v = reinterpret_cast<const float4*>(x + (size_t)node * 128)[c4];
                *reinterpret_cast<float4*>(As + r * ASTR + c4 * 4) = v;
            }
            __syncthreads();
        }
        for (int ck = 0; ck < 8; ck++) {
            __syncthreads();
            for (int i = tid; i < 512; i += 256) {
                int row = i >> 5, c4 = i & 31;
                *reinterpret_cast<float4*>(Ws + row * WSTR + c4 * 4) =
                    reinterpret_cast<const float4*>(Wsrc)[(ck * 16 + row) * 32 + c4];
            }
            __syncthreads();
#pragma unroll
            for (int k0 = 0; k0 < 16; k0 += 8) {
                FragA af;
                wmma::load_matrix_sync(af, As + wr * 16 * ASTR + ck * 16 + k0, ASTR);
                cvt_tf32(af);
#pragma unroll
                for (int j = 0; j < 4; j++) {
                    FragB bf;
                    wmma::load_matrix_sync(bf, Ws + k0 * WSTR + wc * 64 + j * 16, WSTR);
                    cvt_tf32(bf);
                    wmma::mma_sync(acc[j], af, bf, acc[j]);
                }
            }
        }
    }

    // ---- phase 1 epilogue: acc -> Hs, bias+relu (smem only) ----
    __syncthreads();
#pragma unroll
    for (int j = 0; j < 4; j++)
        wmma::store_matrix_sync(Hs + wr * 16 * ASTR + wc * 64 + j * 16, acc[j],
                                ASTR, wmma::mem_row_major);
    __syncthreads();
    for (int i = tid; i < 2048; i += 256) {
        int r = i >> 5, c4 = i & 31;
        float4 v = *reinterpret_cast<float4*>(Hs + r * ASTR + c4 * 4);
        float4 bb = reinterpret_cast<const float4*>(b1)[c4];
        v.x = fmaxf(v.x + bb.x, 0.f);
        v.y = fmaxf(v.y + bb.y, 0.f);
        v.z = fmaxf(v.z + bb.z, 0.f);
        v.w = fmaxf(v.w + bb.w, 0.f);
        *reinterpret_cast<float4*>(Hs + r * ASTR + c4 * 4) = v;
    }

    // ---- phase 2: t2 = Hs @ W2l ; o_part = Hs @ W2r (shared Hs reads) ----
    const int r2 = wid >> 1;
    const int cb = (wid & 1) * 2;
    FragC a2[2], a3[2];
    wmma::fill_fragment(a2[0], 0.0f);
    wmma::fill_fragment(a2[1], 0.0f);
    wmma::fill_fragment(a3[0], 0.0f);
    wmma::fill_fragment(a3[1], 0.0f);

    for (int ck = 0; ck < 8; ck++) {
        __syncthreads();
        {   // stage W2l and W2r chunks [16 x 64] each: 256 float4 apiece
            int row = tid >> 4, c4 = tid & 15;
            *reinterpret_cast<float4*>(W2s + row * W2STR + c4 * 4) =
                reinterpret_cast<const float4*>(W2l)[(ck * 16 + row) * 16 + c4];
            *reinterpret_cast<float4*>(W3s + row * W2STR + c4 * 4) =
                reinterpret_cast<const float4*>(W2r)[(ck * 16 + row) * 16 + c4];
        }
        __syncthreads();
#pragma unroll
        for (int k0 = 0; k0 < 16; k0 += 8) {
            FragA af;
            wmma::load_matrix_sync(af, Hs + r2 * 16 * ASTR + ck * 16 + k0, ASTR);
            cvt_tf32(af);
#pragma unroll
            for (int j = 0; j < 2; j++) {
                FragB bf;
                wmma::load_matrix_sync(bf, W2s + k0 * W2STR + (cb + j) * 16, W2STR);
                cvt_tf32(bf);
                wmma::mma_sync(a2[j], af, bf, a2[j]);
                FragB bf2;
                wmma::load_matrix_sync(bf2, W3s + k0 * W2STR + (cb + j) * 16, W2STR);
                cvt_tf32(bf2);
                wmma::mma_sync(a3[j], af, bf2, a3[j]);
            }
        }
    }
#pragma unroll
    for (int j = 0; j < 2; j++) {
        wmma::store_matrix_sync(g_t2 + (size_t)(base + r2 * 16) * 64 + (cb + j) * 16,
                                a2[j], 64, wmma::mem_row_major);   // padded
        wmma::store_matrix_sync(g_opart + (size_t)(base + r2 * 16) * 64 + (cb + j) * 16,
                                a3[j], 64, wmma::mem_row_major);   // padded
    }
}

// ---------------- final kernel: out = mean-gather(t2) + o_part + b2 ------------
__global__ void __launch_bounds__(256)
out_gather_kernel(const float* __restrict__ b2, float* __restrict__ outp, int N) {
    int node = (int)(((size_t)blockIdx.x * blockDim.x + threadIdx.x) >> 5);
    int lane = threadIdx.x & 31;
    if (node >= N) return;
    int beg = g_rowptr[node];
    int end = g_rowptr[node + 1];
    float2 a0 = make_float2(0.f, 0.f);
    float2 a1 = make_float2(0.f, 0.f);
    int i = beg;
    for (; i + 1 < end; i += 2) {
        int s0 = g_csr[i];
        int s1 = g_csr[i + 1];
        float2 v0 = reinterpret_cast<const float2*>(g_t2 + (size_t)s0 * 64)[lane];
        float2 v1 = reinterpret_cast<const float2*>(g_t2 + (size_t)s1 * 64)[lane];
        a0.x += v0.x; a0.y += v0.y;
        a1.x += v1.x; a1.y += v1.y;
    }
    if (i < end) {
        int s0 = g_csr[i];
        float2 v0 = reinterpret_cast<const float2*>(g_t2 + (size_t)s0 * 64)[lane];
        a0.x += v0.x; a0.y += v0.y;
    }
    int deg = end - beg;
    float rd = (deg > 0) ? (1.0f / (float)deg) : 0.0f;
    float2 op = reinterpret_cast<const float2*>(g_opart + (size_t)node * 64)[lane];
    float2 bb = reinterpret_cast<const float2*>(b2)[lane];
    float2 r;
    r.x = (a0.x + a1.x) * rd + op.x + bb.x;
    r.y = (a0.y + a1.y) * rd + op.y + bb.y;
    reinterpret_cast<float2*>(outp + (size_t)node * 64)[lane] = r;
}

// ---------------- launch -------------------------------------------------------
extern "C" void kernel_launch(void* const* d_in, const int* in_sizes, int n_in,
                              void* d_out, int out_size) {
    const float* x       = (const float*)d_in[0];
    const int*   ei_w    = (const int*)d_in[1];
    const float* W1l     = (const float*)d_in[2];
    const float* b1      = (const float*)d_in[3];
    const float* W1r     = (const float*)d_in[4];
    const float* W2l     = (const float*)d_in[5];
    const float* b2      = (const float*)d_in[6];
    const float* W2r     = (const float*)d_in[7];
    float* out = (float*)d_out;

    int N = in_sizes[0] / 128;
    int E = in_sizes[1] / 2;
    int nblk = (N + SCAN_BLK - 1) / SCAN_BLK;

    // --- decode + CSR build ---
    detect_zero_kernel<<<nblk + 1, 256>>>(ei_w, N, nblk);
    convert_hist_kernel<<<(E + 255) / 256, 256>>>(ei_w, E, N);
    scan_blk_kernel<<<nblk, SCAN_BLK>>>(N);
    scan_finish_kernel<<<nblk, SCAN_BLK>>>(nblk, N);
    fill_kernel<<<(E + 255) / 256, 256>>>(E);

    // --- layer 1 gather + dual GEMM + both layer-2 transforms ---
    gemm1_mega<<<(N + 63) / 64, 256>>>(x, W1l, W1r, b1, W2l, W2r, N);

    // --- final: gather t2-mean + add o_part + bias ---
    {
        size_t threads = (size_t)N * 32;
        out_gather_kernel<<<(int)((threads + 255) / 256), 256>>>(b2, out, N);
    }
}